// round 11
// baseline (speedup 1.0000x reference)
#include <cuda_runtime.h>
#include <math.h>
#include <stdint.h>

#define B_SZ 32768
#define H_SZ 1024
#define C_SZ 10
#define KEEP_SCALE 2.0f
#define LRELU_SLOPE 0.01f

// Scratch (device globals — allocation is forbidden)
__device__ float g_z[(size_t)B_SZ * H_SZ];   // pre-activation
__device__ float g_h[(size_t)B_SZ * H_SZ];   // activation * mask * 2
__device__ float g_ps3[B_SZ];                // partial softmax sums (zero-init,
__device__ float g_ps4[B_SZ];                // re-zeroed by act each layer)

// ===========================================================================
// Helpers
// ===========================================================================
__device__ __forceinline__ uint32_t smem_u32(const void* p) {
    uint32_t a;
    asm("{ .reg .u64 t; cvta.to.shared.u64 t, %1; cvt.u32.u64 %0, t; }"
        : "=r"(a) : "l"(p));
    return a;
}

__device__ __forceinline__ void cp_async16(uint32_t dst, const void* src, int src_bytes) {
    asm volatile("cp.async.cg.shared.global [%0], [%1], 16, %2;"
                 :: "r"(dst), "l"(src), "r"(src_bytes) : "memory");
}

__device__ __forceinline__ float tanh_fast(float x) {
    float r;
    asm("tanh.approx.f32 %0, %1;" : "=f"(r) : "f"(x));
    return r;
}

__device__ __forceinline__ void mma_tf32(float* d, const uint32_t* a, const uint32_t* b) {
    asm volatile(
        "mma.sync.aligned.m16n8k8.row.col.f32.tf32.tf32.f32 "
        "{%0,%1,%2,%3}, {%4,%5,%6,%7}, {%8,%9}, {%0,%1,%2,%3};"
        : "+f"(d[0]), "+f"(d[1]), "+f"(d[2]), "+f"(d[3])
        : "r"(a[0]), "r"(a[1]), "r"(a[2]), "r"(a[3]), "r"(b[0]), "r"(b[1]));
}

// ===========================================================================
// tf32 mma.sync GEMM (R6 config) + fused restricted-softmax partial sums.
// Z[m,n] = sum_k A[m,k]*W[n,k] + bias[n]; epilogue also accumulates
// ps3[m] += sum_{n: tid[n]==3} exp(Z), ps4[m] += sum_{n: tid[n]==4} exp(-Z).
// CTA 128x256, BK=32, 256 threads (8 warps 2x4, warp tile 64x64).
// ===========================================================================
#define BM 128
#define BN 256
#define BK 32
#define PAD 36
#define NSTAGE 4
#define STG_FLOATS ((BM + BN) * PAD)            // 13824 floats
#define GEMM_SMEM (NSTAGE * STG_FLOATS * 4)     // 221184 bytes

template <int K>
__global__ __launch_bounds__(256, 1)
void gemm_tf32_nt(const float* __restrict__ A, const float* __restrict__ W,
                  const float* __restrict__ bias, const int* __restrict__ tids,
                  float* __restrict__ Z,
                  float* __restrict__ ps3, float* __restrict__ ps4)
{
    constexpr int NK = (K + BK - 1) / BK;

    extern __shared__ __align__(16) float sm[];
    __shared__ int stids[BN];

    const int tid  = threadIdx.x;
    const int wid  = tid >> 5;
    const int lane = tid & 31;
    const int g    = lane >> 2;   // groupID (0..7)
    const int tig  = lane & 3;    // thread-in-group (0..3)
    const int warpM = (wid & 1) * 64;       // 2 warp-rows
    const int warpN = (wid >> 1) * 64;      // 4 warp-cols
    const int bm = blockIdx.y * BM;
    const int bn = blockIdx.x * BN;

    stids[tid] = tids[bn + tid];

    const float* Ag = A + (size_t)bm * K;
    const float* Wg = W + (size_t)bn * K;

    float acc[4][8][4];
#pragma unroll
    for (int i = 0; i < 4; i++)
#pragma unroll
        for (int j = 0; j < 8; j++)
#pragma unroll
            for (int q = 0; q < 4; q++) acc[i][j][q] = 0.f;

    auto load_stage = [&](int s, int kc) {
        const int k0 = kc * BK;
        float* As = sm + s * STG_FLOATS;
        float* Bs = As + BM * PAD;
#pragma unroll
        for (int it = 0; it < 4; it++) {
            int idx = tid + it * 256;
            int row = idx >> 3, q = idx & 7;
            int gk  = k0 + q * 4;
            int sb  = (K % BK == 0) ? 16 : ((gk < K) ? 16 : 0);
            int gkc = (K % BK == 0) ? gk : min(gk, K - 4);
            cp_async16(smem_u32(&As[row * PAD + q * 4]),
                       Ag + (size_t)row * K + gkc, sb);
        }
#pragma unroll
        for (int it = 0; it < 8; it++) {
            int idx = tid + it * 256;
            int row = idx >> 3, q = idx & 7;
            int gk  = k0 + q * 4;
            int sb  = (K % BK == 0) ? 16 : ((gk < K) ? 16 : 0);
            int gkc = (K % BK == 0) ? gk : min(gk, K - 4);
            cp_async16(smem_u32(&Bs[row * PAD + q * 4]),
                       Wg + (size_t)row * K + gkc, sb);
        }
    };

    // Prologue
#pragma unroll
    for (int s = 0; s < NSTAGE - 1; s++) {
        load_stage(s, s);
        asm volatile("cp.async.commit_group;" ::: "memory");
    }

#pragma unroll 1
    for (int ki = 0; ki < NK; ki++) {
        asm volatile("cp.async.wait_group 2;" ::: "memory");
        __syncthreads();

        const float* As = sm + (ki & 3) * STG_FLOATS;
        const float* Bs = As + BM * PAD;

#pragma unroll
        for (int ks = 0; ks < 4; ks++) {
            const int kb = 8 * ks + tig;

            uint32_t af[4][4];
#pragma unroll
            for (int i = 0; i < 4; i++) {
                int base = (warpM + 16 * i + g) * PAD + kb;
                af[i][0] = __float_as_uint(As[base]);
                af[i][1] = __float_as_uint(As[base + 8 * PAD]);
                af[i][2] = __float_as_uint(As[base + 4]);
                af[i][3] = __float_as_uint(As[base + 8 * PAD + 4]);
            }
            uint32_t bf[8][2];
#pragma unroll
            for (int j = 0; j < 8; j++) {
                int base = (warpN + 8 * j + g) * PAD + kb;
                bf[j][0] = __float_as_uint(Bs[base]);
                bf[j][1] = __float_as_uint(Bs[base + 4]);
            }
#pragma unroll
            for (int i = 0; i < 4; i++)
#pragma unroll
                for (int j = 0; j < 8; j++)
                    mma_tf32(acc[i][j], af[i], bf[j]);
        }

        const int kn = ki + NSTAGE - 1;
        if (kn < NK) load_stage(kn & 3, kn);
        asm volatile("cp.async.commit_group;" ::: "memory");
    }

    // Epilogue: bias + store + fused softmax/softmin partial sums.
#pragma unroll
    for (int i = 0; i < 4; i++) {
        int rowA = bm + warpM + 16 * i + g;    // and rowA+8
        float a3 = 0.f, a4 = 0.f, b3 = 0.f, b4 = 0.f;
#pragma unroll
        for (int j = 0; j < 8; j++) {
            int lc  = warpN + 8 * j + 2 * tig;
            int col = bn + lc;
            float2 bi = *reinterpret_cast<const float2*>(&bias[col]);
            float z00 = acc[i][j][0] + bi.x, z01 = acc[i][j][1] + bi.y;
            float z10 = acc[i][j][2] + bi.x, z11 = acc[i][j][3] + bi.y;
            int ty0 = stids[lc], ty1 = stids[lc + 1];
            if (ty0 == 3) { a3 += __expf(z00);  b3 += __expf(z10); }
            if (ty0 == 4) { a4 += __expf(-z00); b4 += __expf(-z10); }
            if (ty1 == 3) { a3 += __expf(z01);  b3 += __expf(z11); }
            if (ty1 == 4) { a4 += __expf(-z01); b4 += __expf(-z11); }
            *reinterpret_cast<float2*>(&Z[(size_t)rowA * H_SZ + col]) =
                make_float2(z00, z01);
            *reinterpret_cast<float2*>(&Z[(size_t)(rowA + 8) * H_SZ + col]) =
                make_float2(z10, z11);
        }
        // reduce over tig (lanes g*4 + {0..3})
        a3 += __shfl_xor_sync(0xffffffffu, a3, 1);
        a3 += __shfl_xor_sync(0xffffffffu, a3, 2);
        a4 += __shfl_xor_sync(0xffffffffu, a4, 1);
        a4 += __shfl_xor_sync(0xffffffffu, a4, 2);
        b3 += __shfl_xor_sync(0xffffffffu, b3, 1);
        b3 += __shfl_xor_sync(0xffffffffu, b3, 2);
        b4 += __shfl_xor_sync(0xffffffffu, b4, 1);
        b4 += __shfl_xor_sync(0xffffffffu, b4, 2);
        if (tig == 0) {                       // cross warp-column + cross-CTA
            atomicAdd(&ps3[rowA], a3);
            atomicAdd(&ps4[rowA], a4);
            atomicAdd(&ps3[rowA + 8], b3);
            atomicAdd(&ps4[rowA + 8], b4);
        }
    }
}

// ===========================================================================
// Mixed activation v5: reduction-free (softmax sums come from GEMM epilogue).
// Re-zeros psum slots for determinism. Fused mask*2 + mask pass-through.
// ===========================================================================
__global__ __launch_bounds__(256)
void act_kernel(const float* __restrict__ Z, const int* __restrict__ tids,
                const float* __restrict__ mask, float* __restrict__ Hout,
                float* __restrict__ MOut,
                float* __restrict__ ps3, float* __restrict__ ps4)
{
    const int row = blockIdx.x;
    const int t   = threadIdx.x;
    const size_t base = (size_t)row * H_SZ;

    float s3v = ps3[row], s4v = ps4[row];   // broadcast load
    __syncthreads();                         // all reads before re-zero
    if (t == 0) { ps3[row] = 0.f; ps4[row] = 0.f; }
    float r3 = __frcp_rn(s3v), r4 = __frcp_rn(s4v);

    float4 z4 = *reinterpret_cast<const float4*>(Z + base + t * 4);
    int4  i4 = *reinterpret_cast<const int4*>(tids + t * 4);
    float zr[4] = {z4.x, z4.y, z4.z, z4.w};
    int   tr[4] = {i4.x, i4.y, i4.z, i4.w};

    float4 mk = *reinterpret_cast<const float4*>(mask + base + t * 4);
    float mv[4] = {mk.x, mk.y, mk.z, mk.w};
    float ov[4];
#pragma unroll
    for (int q = 0; q < 4; q++) {
        float x = zr[q], v;
        switch (tr[q]) {
            case 0:  v = fmaxf(x, 0.f); break;
            case 1:  v = tanh_fast(x); break;
            case 2:  v = fmaf(0.5f, tanh_fast(0.5f * x), 0.5f); break; // sigmoid
            case 3:  v = __expf(x) * r3; break;
            case 4:  v = __expf(-x) * r4; break;
            case 5:  v = x * normcdff(x); break;   // exact gelu
            default: v = (x >= 0.f) ? x : LRELU_SLOPE * x; break;
        }
        ov[q] = v * mv[q] * KEEP_SCALE;
    }
    *reinterpret_cast<float4*>(Hout + base + t * 4) =
        make_float4(ov[0], ov[1], ov[2], ov[3]);
    *reinterpret_cast<float4*>(MOut + base + t * 4) = mk;   // fused pass-through
}

// ===========================================================================
// Layer 3 + log_softmax: logits = Hm @ W3^T + b3 (C=10), then log_softmax.
// Warp handles 8 rows; W3 fragments hoisted per j-chunk, reused across rows.
// ===========================================================================
__global__ __launch_bounds__(256)
void layer3_kernel(const float* __restrict__ Hm, const float* __restrict__ W3,
                   const float* __restrict__ b3, float* __restrict__ Out)
{
    __shared__ float Ws[C_SZ * H_SZ];
    __shared__ float bs[16];
    for (int i = threadIdx.x; i < C_SZ * H_SZ; i += 256) Ws[i] = W3[i];
    if (threadIdx.x < C_SZ) bs[threadIdx.x] = b3[threadIdx.x];
    __syncthreads();

    const int warp = threadIdx.x >> 5;
    const int lane = threadIdx.x & 31;
    const int row0 = blockIdx.x * 64 + warp * 8;   // 8 rows per warp
    const float4* Ws4 = reinterpret_cast<const float4*>(Ws);

    float acc[8][C_SZ];
#pragma unroll
    for (int r = 0; r < 8; r++)
#pragma unroll
        for (int c = 0; c < C_SZ; c++) acc[r][c] = 0.f;

#pragma unroll
    for (int j = 0; j < 8; j++) {
        int idx = lane + 32 * j;
        float4 wv[C_SZ];
#pragma unroll
        for (int c = 0; c < C_SZ; c++) wv[c] = Ws4[c * 256 + idx];
#pragma unroll
        for (int r = 0; r < 8; r++) {
            float4 hv = *reinterpret_cast<const float4*>(
                &Hm[(size_t)(row0 + r) * H_SZ + idx * 4]);
#pragma unroll
            for (int c = 0; c < C_SZ; c++)
                acc[r][c] += hv.x * wv[c].x + hv.y * wv[c].y
                           + hv.z * wv[c].z + hv.w * wv[c].w;
        }
    }

#pragma unroll
    for (int r = 0; r < 8; r++) {
#pragma unroll
        for (int c = 0; c < C_SZ; c++)
#pragma unroll
            for (int off = 16; off; off >>= 1)
                acc[r][c] += __shfl_xor_sync(0xffffffff, acc[r][c], off);

        if (lane == 0) {
            float l[C_SZ], mx = -INFINITY;
#pragma unroll
            for (int c = 0; c < C_SZ; c++) {
                l[c] = acc[r][c] + bs[c];
                mx = fmaxf(mx, l[c]);
            }
            float s = 0.f;
#pragma unroll
            for (int c = 0; c < C_SZ; c++) s += __expf(l[c] - mx);
            float lse = mx + __logf(s);
#pragma unroll
            for (int c = 0; c < C_SZ; c++)
                Out[(size_t)(row0 + r) * C_SZ + c] = l[c] - lse;
        }
    }
}

// ===========================================================================
extern "C" void kernel_launch(void* const* d_in, const int* in_sizes, int n_in,
                              void* d_out, int out_size)
{
    (void)in_sizes; (void)n_in; (void)out_size;
    const float* x    = (const float*)d_in[0];
    const float* W0   = (const float*)d_in[1];
    const float* b0   = (const float*)d_in[2];
    const float* W1   = (const float*)d_in[3];
    const float* b1   = (const float*)d_in[4];
    const float* W2   = (const float*)d_in[5];
    const float* b2   = (const float*)d_in[6];
    const float* W3   = (const float*)d_in[7];
    const float* b3   = (const float*)d_in[8];
    const float* m1   = (const float*)d_in[9];
    const float* m2   = (const float*)d_in[10];
    const float* m3   = (const float*)d_in[11];
    const int*   tids = (const int*)d_in[12];
    float* out = (float*)d_out;

    float *z, *h, *ps3, *ps4;
    cudaGetSymbolAddress((void**)&z, g_z);
    cudaGetSymbolAddress((void**)&h, g_h);
    cudaGetSymbolAddress((void**)&ps3, g_ps3);
    cudaGetSymbolAddress((void**)&ps4, g_ps4);

    cudaFuncSetAttribute(gemm_tf32_nt<784>,
                         cudaFuncAttributeMaxDynamicSharedMemorySize, GEMM_SMEM);
    cudaFuncSetAttribute(gemm_tf32_nt<1024>,
                         cudaFuncAttributeMaxDynamicSharedMemorySize, GEMM_SMEM);

    dim3 grid(H_SZ / BN, B_SZ / BM);   // (4, 256)
    float* mout = out + (size_t)B_SZ * C_SZ;
    size_t BH = (size_t)B_SZ * H_SZ;

    gemm_tf32_nt<784><<<grid, 256, GEMM_SMEM>>>(x, W0, b0, tids, z, ps3, ps4);
    act_kernel<<<B_SZ, 256>>>(z, tids, m1, h, mout, ps3, ps4);

    gemm_tf32_nt<1024><<<grid, 256, GEMM_SMEM>>>(h, W1, b1, tids + H_SZ, z, ps3, ps4);
    act_kernel<<<B_SZ, 256>>>(z, tids + H_SZ, m2, h, mout + BH, ps3, ps4);

    gemm_tf32_nt<1024><<<grid, 256, GEMM_SMEM>>>(h, W2, b2, tids + 2 * H_SZ, z, ps3, ps4);
    act_kernel<<<B_SZ, 256>>>(z, tids + 2 * H_SZ, m3, h, mout + 2 * BH, ps3, ps4);

    layer3_kernel<<<B_SZ / 64, 256>>>(h, W3, b3, out);
}

// round 12
// speedup vs baseline: 1.2181x; 1.2181x over previous
#include <cuda_runtime.h>
#include <math.h>
#include <stdint.h>

#define B_SZ 32768
#define H_SZ 1024
#define C_SZ 10
#define KEEP_SCALE 2.0f
#define LRELU_SLOPE 0.01f

// Scratch (device globals — allocation is forbidden)
__device__ float g_z[(size_t)B_SZ * H_SZ];   // pre-activation
__device__ float g_h[(size_t)B_SZ * H_SZ];   // activation * mask * 2

// ===========================================================================
// Helpers
// ===========================================================================
__device__ __forceinline__ uint32_t smem_u32(const void* p) {
    uint32_t a;
    asm("{ .reg .u64 t; cvta.to.shared.u64 t, %1; cvt.u32.u64 %0, t; }"
        : "=r"(a) : "l"(p));
    return a;
}

__device__ __forceinline__ void cp_async16(uint32_t dst, const void* src, int src_bytes) {
    asm volatile("cp.async.cg.shared.global [%0], [%1], 16, %2;"
                 :: "r"(dst), "l"(src), "r"(src_bytes) : "memory");
}

__device__ __forceinline__ float tanh_fast(float x) {
    float r;
    asm("tanh.approx.f32 %0, %1;" : "=f"(r) : "f"(x));
    return r;
}

__device__ __forceinline__ float act_eval(float x, int ty, float r3, float r4) {
    float v;
    switch (ty) {
        case 0:  v = fmaxf(x, 0.f); break;
        case 1:  v = tanh_fast(x); break;
        case 2:  v = fmaf(0.5f, tanh_fast(0.5f * x), 0.5f); break; // sigmoid
        case 3:  v = __expf(x) * r3; break;
        case 4:  v = __expf(-x) * r4; break;
        case 5:  v = x * normcdff(x); break;   // exact gelu
        default: v = (x >= 0.f) ? x : LRELU_SLOPE * x; break;
    }
    return v;
}

__device__ __forceinline__ void mma_tf32(float* d, const uint32_t* a, const uint32_t* b) {
    asm volatile(
        "mma.sync.aligned.m16n8k8.row.col.f32.tf32.tf32.f32 "
        "{%0,%1,%2,%3}, {%4,%5,%6,%7}, {%8,%9}, {%0,%1,%2,%3};"
        : "+f"(d[0]), "+f"(d[1]), "+f"(d[2]), "+f"(d[3])
        : "r"(a[0]), "r"(a[1]), "r"(a[2]), "r"(a[3]), "r"(b[0]), "r"(b[1]));
}

// ===========================================================================
// tf32 mma.sync GEMM (validated R6/R8 config): Z = A @ W^T + bias
// CTA 128x256, BK=32, 256 threads (8 warps 2x4, warp tile 64x64).
// ===========================================================================
#define BM 128
#define BN 256
#define BK 32
#define PAD 36
#define NSTAGE 4
#define STG_FLOATS ((BM + BN) * PAD)            // 13824 floats
#define GEMM_SMEM (NSTAGE * STG_FLOATS * 4)     // 221184 bytes

template <int K>
__global__ __launch_bounds__(256, 1)
void gemm_tf32_nt(const float* __restrict__ A, const float* __restrict__ W,
                  const float* __restrict__ bias, float* __restrict__ Z)
{
    constexpr int NK = (K + BK - 1) / BK;

    extern __shared__ __align__(16) float sm[];

    const int tid  = threadIdx.x;
    const int wid  = tid >> 5;
    const int lane = tid & 31;
    const int g    = lane >> 2;   // groupID (0..7)
    const int tig  = lane & 3;    // thread-in-group (0..3)
    const int warpM = (wid & 1) * 64;       // 2 warp-rows
    const int warpN = (wid >> 1) * 64;      // 4 warp-cols
    const int bm = blockIdx.y * BM;
    const int bn = blockIdx.x * BN;

    const float* Ag = A + (size_t)bm * K;
    const float* Wg = W + (size_t)bn * K;

    float acc[4][8][4];
#pragma unroll
    for (int i = 0; i < 4; i++)
#pragma unroll
        for (int j = 0; j < 8; j++)
#pragma unroll
            for (int q = 0; q < 4; q++) acc[i][j][q] = 0.f;

    auto load_stage = [&](int s, int kc) {
        const int k0 = kc * BK;
        float* As = sm + s * STG_FLOATS;
        float* Bs = As + BM * PAD;
#pragma unroll
        for (int it = 0; it < 4; it++) {
            int idx = tid + it * 256;
            int row = idx >> 3, q = idx & 7;
            int gk  = k0 + q * 4;
            int sb  = (K % BK == 0) ? 16 : ((gk < K) ? 16 : 0);
            int gkc = (K % BK == 0) ? gk : min(gk, K - 4);
            cp_async16(smem_u32(&As[row * PAD + q * 4]),
                       Ag + (size_t)row * K + gkc, sb);
        }
#pragma unroll
        for (int it = 0; it < 8; it++) {
            int idx = tid + it * 256;
            int row = idx >> 3, q = idx & 7;
            int gk  = k0 + q * 4;
            int sb  = (K % BK == 0) ? 16 : ((gk < K) ? 16 : 0);
            int gkc = (K % BK == 0) ? gk : min(gk, K - 4);
            cp_async16(smem_u32(&Bs[row * PAD + q * 4]),
                       Wg + (size_t)row * K + gkc, sb);
        }
    };

    // Prologue
#pragma unroll
    for (int s = 0; s < NSTAGE - 1; s++) {
        load_stage(s, s);
        asm volatile("cp.async.commit_group;" ::: "memory");
    }

#pragma unroll 1
    for (int ki = 0; ki < NK; ki++) {
        asm volatile("cp.async.wait_group 2;" ::: "memory");
        __syncthreads();

        const float* As = sm + (ki & 3) * STG_FLOATS;
        const float* Bs = As + BM * PAD;

#pragma unroll
        for (int ks = 0; ks < 4; ks++) {
            const int kb = 8 * ks + tig;

            uint32_t af[4][4];
#pragma unroll
            for (int i = 0; i < 4; i++) {
                int base = (warpM + 16 * i + g) * PAD + kb;
                af[i][0] = __float_as_uint(As[base]);
                af[i][1] = __float_as_uint(As[base + 8 * PAD]);
                af[i][2] = __float_as_uint(As[base + 4]);
                af[i][3] = __float_as_uint(As[base + 8 * PAD + 4]);
            }
            uint32_t bf[8][2];
#pragma unroll
            for (int j = 0; j < 8; j++) {
                int base = (warpN + 8 * j + g) * PAD + kb;
                bf[j][0] = __float_as_uint(Bs[base]);
                bf[j][1] = __float_as_uint(Bs[base + 4]);
            }
#pragma unroll
            for (int i = 0; i < 4; i++)
#pragma unroll
                for (int j = 0; j < 8; j++)
                    mma_tf32(acc[i][j], af[i], bf[j]);
        }

        const int kn = ki + NSTAGE - 1;
        if (kn < NK) load_stage(kn & 3, kn);
        asm volatile("cp.async.commit_group;" ::: "memory");
    }

    // Epilogue: bias + store
#pragma unroll
    for (int i = 0; i < 4; i++) {
        int row0 = bm + warpM + 16 * i + g;
#pragma unroll
        for (int j = 0; j < 8; j++) {
            int col = bn + warpN + 8 * j + 2 * tig;
            float2 bi = *reinterpret_cast<const float2*>(&bias[col]);
            float2 v0 = make_float2(acc[i][j][0] + bi.x, acc[i][j][1] + bi.y);
            float2 v1 = make_float2(acc[i][j][2] + bi.x, acc[i][j][3] + bi.y);
            *reinterpret_cast<float2*>(&Z[(size_t)row0 * H_SZ + col]) = v0;
            *reinterpret_cast<float2*>(&Z[(size_t)(row0 + 8) * H_SZ + col]) = v1;
        }
    }
}

// ===========================================================================
// Mixed activation v4 (R8-validated): E cached from reduction phase;
// relu/lrelu merged; tanh&sigmoid share one tanh.approx; gelu exact.
// Softmax/softmin without max-subtraction. Fused mask pass-through.
// ===========================================================================
__global__ __launch_bounds__(256)
void act_kernel(const float* __restrict__ Z, const int* __restrict__ tids,
                const float* __restrict__ mask, float* __restrict__ Hout,
                float* __restrict__ MOut)
{
    const int row  = blockIdx.x;
    const int t    = threadIdx.x;
    const int lane = t & 31, wid = t >> 5;
    const size_t base = (size_t)row * H_SZ;

    float4 z4 = *reinterpret_cast<const float4*>(Z + base + t * 4);
    int4  i4 = *reinterpret_cast<const int4*>(tids + t * 4);
    float zr[4] = {z4.x, z4.y, z4.z, z4.w};
    int   tr[4] = {i4.x, i4.y, i4.z, i4.w};

    // Phase 1: exp for softmax/softmin lanes (cache E), reduce sums.
    float E[4];
    float s3 = 0.f, s4 = 0.f;
#pragma unroll
    for (int q = 0; q < 4; q++) {
        bool p3 = (tr[q] == 3), p4 = (tr[q] == 4);
        float sg = p4 ? -zr[q] : zr[q];
        E[q] = __expf(sg);
        s3 += p3 ? E[q] : 0.f;
        s4 += p4 ? E[q] : 0.f;
    }
#pragma unroll
    for (int off = 16; off; off >>= 1) {
        s3 += __shfl_xor_sync(0xffffffffu, s3, off);
        s4 += __shfl_xor_sync(0xffffffffu, s4, off);
    }
    __shared__ float sC[8], sD[8];
    if (lane == 0) { sC[wid] = s3; sD[wid] = s4; }
    __syncthreads();
    s3 = 0.f; s4 = 0.f;
#pragma unroll
    for (int j = 0; j < 8; j++) { s3 += sC[j]; s4 += sD[j]; }
    float r3 = __frcp_rn(s3), r4 = __frcp_rn(s4);

    float4 mk = *reinterpret_cast<const float4*>(mask + base + t * 4);
    float mv[4] = {mk.x, mk.y, mk.z, mk.w};
    float ov[4];
#pragma unroll
    for (int q = 0; q < 4; q++) {
        float x = zr[q];
        int  ty = tr[q];
        float cmin  = (ty == 6) ? LRELU_SLOPE : 0.f;
        float vrelu = fmaxf(x, 0.f) + cmin * fminf(x, 0.f);
        float targ  = (ty == 2) ? 0.5f * x : x;
        float th    = tanh_fast(targ);
        float vtanh = (ty == 2) ? fmaf(0.5f, th, 0.5f) : th;
        float vsoft = E[q] * ((ty == 3) ? r3 : r4);
        float v = (ty <= 0) ? vrelu
                : (ty <= 2) ? vtanh
                : (ty <= 4) ? vsoft
                : vrelu;
        if (ty == 5) v = x * normcdff(x);
        ov[q] = v * mv[q] * KEEP_SCALE;
    }
    *reinterpret_cast<float4*>(Hout + base + t * 4) =
        make_float4(ov[0], ov[1], ov[2], ov[3]);
    *reinterpret_cast<float4*>(MOut + base + t * 4) = mk;
}

// ===========================================================================
// FUSED act3 + layer3 + log_softmax.
// Reads z (layer-2 pre-activation), tids row 2, mask3; computes
// h = act(z)*mask*2 inline (pass A: warp-local softmax sums; pass B: apply
// act + FMA against smem W3), writes logits' log_softmax and the mask3
// pass-through. No h round-trip through DRAM.
// ===========================================================================
__global__ __launch_bounds__(256)
void layer3_fused_kernel(const float* __restrict__ Z, const int* __restrict__ tids,
                         const float* __restrict__ mask,
                         const float* __restrict__ W3, const float* __restrict__ b3,
                         float* __restrict__ Out, float* __restrict__ MOut)
{
    __shared__ float Ws[C_SZ * H_SZ];
    __shared__ float bs[16];
    __shared__ int   st[H_SZ];
    for (int i = threadIdx.x; i < C_SZ * H_SZ; i += 256) Ws[i] = W3[i];
    for (int i = threadIdx.x; i < H_SZ; i += 256) st[i] = tids[i];
    if (threadIdx.x < C_SZ) bs[threadIdx.x] = b3[threadIdx.x];
    __syncthreads();

    const int warp = threadIdx.x >> 5;
    const int lane = threadIdx.x & 31;
    const int row0 = blockIdx.x * 64 + warp * 8;   // 8 rows per warp
    const float4* Ws4 = reinterpret_cast<const float4*>(Ws);
    const int4*   st4 = reinterpret_cast<const int4*>(st);

    // Pass A: per-row restricted softmax/softmin sums (no max-subtraction).
    float r3[8], r4[8];
#pragma unroll
    for (int r = 0; r < 8; r++) {
        float a = 0.f, b = 0.f;
        const size_t zb = (size_t)(row0 + r) * H_SZ;
#pragma unroll
        for (int j = 0; j < 8; j++) {
            int idx = lane + 32 * j;
            float4 z4 = *reinterpret_cast<const float4*>(&Z[zb + idx * 4]);
            int4   t4 = st4[idx];
            float zz[4] = {z4.x, z4.y, z4.z, z4.w};
            int   tt[4] = {t4.x, t4.y, t4.z, t4.w};
#pragma unroll
            for (int q = 0; q < 4; q++) {
                bool p3 = (tt[q] == 3), p4 = (tt[q] == 4);
                float e = __expf(p4 ? -zz[q] : zz[q]);
                a += p3 ? e : 0.f;
                b += p4 ? e : 0.f;
            }
        }
#pragma unroll
        for (int off = 16; off; off >>= 1) {
            a += __shfl_xor_sync(0xffffffffu, a, off);
            b += __shfl_xor_sync(0xffffffffu, b, off);
        }
        r3[r] = __frcp_rn(a);
        r4[r] = __frcp_rn(b);
    }

    // Pass B: act inline + FMA with W3 (wv hoisted per j, reused over 8 rows).
    float acc[8][C_SZ];
#pragma unroll
    for (int r = 0; r < 8; r++)
#pragma unroll
        for (int c = 0; c < C_SZ; c++) acc[r][c] = 0.f;

#pragma unroll 2
    for (int j = 0; j < 8; j++) {
        int idx = lane + 32 * j;
        float4 wv[C_SZ];
#pragma unroll
        for (int c = 0; c < C_SZ; c++) wv[c] = Ws4[c * 256 + idx];
        int4 t4 = st4[idx];
        int  tt[4] = {t4.x, t4.y, t4.z, t4.w};
#pragma unroll
        for (int r = 0; r < 8; r++) {
            const size_t rb = (size_t)(row0 + r) * H_SZ;
            float4 z4 = *reinterpret_cast<const float4*>(&Z[rb + idx * 4]);
            float4 mk = *reinterpret_cast<const float4*>(&mask[rb + idx * 4]);
            *reinterpret_cast<float4*>(&MOut[rb + idx * 4]) = mk;  // pass-through
            float hv[4];
            hv[0] = act_eval(z4.x, tt[0], r3[r], r4[r]) * mk.x * KEEP_SCALE;
            hv[1] = act_eval(z4.y, tt[1], r3[r], r4[r]) * mk.y * KEEP_SCALE;
            hv[2] = act_eval(z4.z, tt[2], r3[r], r4[r]) * mk.z * KEEP_SCALE;
            hv[3] = act_eval(z4.w, tt[3], r3[r], r4[r]) * mk.w * KEEP_SCALE;
#pragma unroll
            for (int c = 0; c < C_SZ; c++)
                acc[r][c] += hv[0] * wv[c].x + hv[1] * wv[c].y
                           + hv[2] * wv[c].z + hv[3] * wv[c].w;
        }
    }

#pragma unroll
    for (int r = 0; r < 8; r++) {
#pragma unroll
        for (int c = 0; c < C_SZ; c++)
#pragma unroll
            for (int off = 16; off; off >>= 1)
                acc[r][c] += __shfl_xor_sync(0xffffffff, acc[r][c], off);

        if (lane == 0) {
            float l[C_SZ], mx = -INFINITY;
#pragma unroll
            for (int c = 0; c < C_SZ; c++) {
                l[c] = acc[r][c] + bs[c];
                mx = fmaxf(mx, l[c]);
            }
            float s = 0.f;
#pragma unroll
            for (int c = 0; c < C_SZ; c++) s += __expf(l[c] - mx);
            float lse = mx + __logf(s);
#pragma unroll
            for (int c = 0; c < C_SZ; c++)
                Out[(size_t)(row0 + r) * C_SZ + c] = l[c] - lse;
        }
    }
}

// ===========================================================================
extern "C" void kernel_launch(void* const* d_in, const int* in_sizes, int n_in,
                              void* d_out, int out_size)
{
    (void)in_sizes; (void)n_in; (void)out_size;
    const float* x    = (const float*)d_in[0];
    const float* W0   = (const float*)d_in[1];
    const float* b0   = (const float*)d_in[2];
    const float* W1   = (const float*)d_in[3];
    const float* b1   = (const float*)d_in[4];
    const float* W2   = (const float*)d_in[5];
    const float* b2   = (const float*)d_in[6];
    const float* W3   = (const float*)d_in[7];
    const float* b3   = (const float*)d_in[8];
    const float* m1   = (const float*)d_in[9];
    const float* m2   = (const float*)d_in[10];
    const float* m3   = (const float*)d_in[11];
    const int*   tids = (const int*)d_in[12];
    float* out = (float*)d_out;

    float *z, *h;
    cudaGetSymbolAddress((void**)&z, g_z);
    cudaGetSymbolAddress((void**)&h, g_h);

    cudaFuncSetAttribute(gemm_tf32_nt<784>,
                         cudaFuncAttributeMaxDynamicSharedMemorySize, GEMM_SMEM);
    cudaFuncSetAttribute(gemm_tf32_nt<1024>,
                         cudaFuncAttributeMaxDynamicSharedMemorySize, GEMM_SMEM);

    dim3 grid(H_SZ / BN, B_SZ / BM);   // (4, 256)
    float* mout = out + (size_t)B_SZ * C_SZ;
    size_t BH = (size_t)B_SZ * H_SZ;

    gemm_tf32_nt<784><<<grid, 256, GEMM_SMEM>>>(x, W0, b0, z);
    act_kernel<<<B_SZ, 256>>>(z, tids, m1, h, mout);

    gemm_tf32_nt<1024><<<grid, 256, GEMM_SMEM>>>(h, W1, b1, z);
    act_kernel<<<B_SZ, 256>>>(z, tids + H_SZ, m2, h, mout + BH);

    gemm_tf32_nt<1024><<<grid, 256, GEMM_SMEM>>>(h, W2, b2, z);
    layer3_fused_kernel<<<B_SZ / 64, 256>>>(z, tids + 2 * H_SZ, m3, W3, b3,
                                            out, mout + 2 * BH);
}

// round 13
// speedup vs baseline: 2.6730x; 2.1944x over previous
#include <cuda_runtime.h>
#include <cuda_fp16.h>
#include <math.h>
#include <stdint.h>

#define B_SZ 32768
#define H_SZ 1024
#define D_IN 784
#define C_SZ 10
#define KEEP_SCALE 2.0f
#define LRELU_SLOPE 0.01f

// Scratch (device globals — allocation is forbidden)
__device__ float  g_z[(size_t)B_SZ * H_SZ];        // pre-activation (fp32)
__device__ __half g_h[(size_t)B_SZ * H_SZ];        // activations (fp16)
__device__ __half g_xh[(size_t)B_SZ * D_IN];       // x converted to fp16
__device__ __half g_w0[(size_t)H_SZ * D_IN];       // W0 fp16
__device__ __half g_w1[(size_t)H_SZ * H_SZ];       // W1 fp16
__device__ __half g_w2[(size_t)H_SZ * H_SZ];       // W2 fp16

// ===========================================================================
// Helpers
// ===========================================================================
__device__ __forceinline__ uint32_t smem_u32(const void* p) {
    uint32_t a;
    asm("{ .reg .u64 t; cvta.to.shared.u64 t, %1; cvt.u32.u64 %0, t; }"
        : "=r"(a) : "l"(p));
    return a;
}

__device__ __forceinline__ void cp_async16(uint32_t dst, const void* src, int src_bytes) {
    asm volatile("cp.async.cg.shared.global [%0], [%1], 16, %2;"
                 :: "r"(dst), "l"(src), "r"(src_bytes) : "memory");
}

__device__ __forceinline__ float tanh_fast(float x) {
    float r;
    asm("tanh.approx.f32 %0, %1;" : "=f"(r) : "f"(x));
    return r;
}

__device__ __forceinline__ void mma_f16(float* d, const uint32_t* a, const uint32_t* b) {
    asm volatile(
        "mma.sync.aligned.m16n8k16.row.col.f32.f16.f16.f32 "
        "{%0,%1,%2,%3}, {%4,%5,%6,%7}, {%8,%9}, {%0,%1,%2,%3};"
        : "+f"(d[0]), "+f"(d[1]), "+f"(d[2]), "+f"(d[3])
        : "r"(a[0]), "r"(a[1]), "r"(a[2]), "r"(a[3]), "r"(b[0]), "r"(b[1]));
}

// ===========================================================================
// fp32 -> fp16 conversion (vectorized, n multiple of 1024)
// ===========================================================================
__global__ __launch_bounds__(256)
void cvt_f2h(const float* __restrict__ src, __half* __restrict__ dst) {
    size_t i = ((size_t)blockIdx.x * 256 + threadIdx.x) * 4;
    float4 v = *reinterpret_cast<const float4*>(src + i);
    __half2 h01 = __floats2half2_rn(v.x, v.y);
    __half2 h23 = __floats2half2_rn(v.z, v.w);
    uint2 o = make_uint2(*(uint32_t*)&h01, *(uint32_t*)&h23);
    *reinterpret_cast<uint2*>(dst + i) = o;
}

// ===========================================================================
// fp16 mma.sync GEMM: Z[m,n] = sum_k A[m,k]*W[n,k] + bias[n]  (fp32 out)
// CTA 128x256, BK=64 halves, 256 threads (8 warps 2x4, warp tile 64x64).
// Smem m-major rows of 72 halves (pad -> conflict-free fragment LDS).
// 4-stage cp.async pipeline with zfill for K tail (K multiple of 8).
// ===========================================================================
#define BM 128
#define BN 256
#define BK 64                                   // halves
#define PADH 72                                 // halves per row (36 words)
#define NSTAGE 4
#define STG_HALVES ((BM + BN) * PADH)           // 27648 halves = 55296 B
#define GEMM_SMEM (NSTAGE * STG_HALVES * 2)     // 221184 bytes

template <int K>
__global__ __launch_bounds__(256, 1)
void gemm_f16_nt(const __half* __restrict__ A, const __half* __restrict__ W,
                 const float* __restrict__ bias, float* __restrict__ Z)
{
    constexpr int NK = (K + BK - 1) / BK;

    extern __shared__ __align__(16) __half sm[];

    const int tid  = threadIdx.x;
    const int wid  = tid >> 5;
    const int lane = tid & 31;
    const int g    = lane >> 2;   // groupID (0..7)
    const int tig  = lane & 3;    // thread-in-group (0..3)
    const int warpM = (wid & 1) * 64;       // 2 warp-rows
    const int warpN = (wid >> 1) * 64;      // 4 warp-cols
    const int bm = blockIdx.y * BM;
    const int bn = blockIdx.x * BN;

    const __half* Ag = A + (size_t)bm * K;
    const __half* Wg = W + (size_t)bn * K;

    float acc[4][8][4];
#pragma unroll
    for (int i = 0; i < 4; i++)
#pragma unroll
        for (int j = 0; j < 8; j++)
#pragma unroll
            for (int q = 0; q < 4; q++) acc[i][j][q] = 0.f;

    auto load_stage = [&](int s, int kc) {
        const int k0 = kc * BK;
        __half* As = sm + s * STG_HALVES;
        __half* Bs = As + BM * PADH;
        // A: 128 rows x 8 granules(16B = 8 halves) = 1024 granules
#pragma unroll
        for (int it = 0; it < 4; it++) {
            int idx = tid + it * 256;
            int row = idx >> 3, q = idx & 7;
            int gk  = k0 + q * 8;
            int sb  = (K % BK == 0) ? 16 : ((gk < K) ? 16 : 0);
            int gkc = (K % BK == 0) ? gk : min(gk, K - 8);
            cp_async16(smem_u32(&As[row * PADH + q * 8]),
                       Ag + (size_t)row * K + gkc, sb);
        }
        // B: 256 rows x 8 granules = 2048 granules
#pragma unroll
        for (int it = 0; it < 8; it++) {
            int idx = tid + it * 256;
            int row = idx >> 3, q = idx & 7;
            int gk  = k0 + q * 8;
            int sb  = (K % BK == 0) ? 16 : ((gk < K) ? 16 : 0);
            int gkc = (K % BK == 0) ? gk : min(gk, K - 8);
            cp_async16(smem_u32(&Bs[row * PADH + q * 8]),
                       Wg + (size_t)row * K + gkc, sb);
        }
    };

    // Prologue
#pragma unroll
    for (int s = 0; s < NSTAGE - 1; s++) {
        load_stage(s, s);
        asm volatile("cp.async.commit_group;" ::: "memory");
    }

#pragma unroll 1
    for (int ki = 0; ki < NK; ki++) {
        asm volatile("cp.async.wait_group 2;" ::: "memory");
        __syncthreads();

        const uint32_t* As32 = reinterpret_cast<const uint32_t*>(
            sm + (ki & 3) * STG_HALVES);
        const uint32_t* Bs32 = As32 + BM * (PADH / 2);

#pragma unroll
        for (int ks = 0; ks < 4; ks++) {          // 4 k16-steps per BK=64
            const int kw = ks * 8 + tig;          // word index in row (0..31)

            uint32_t af[4][4];
#pragma unroll
            for (int i = 0; i < 4; i++) {
                int m0 = (warpM + 16 * i + g) * 36;
                af[i][0] = As32[m0 + kw];
                af[i][1] = As32[m0 + 8 * 36 + kw];
                af[i][2] = As32[m0 + kw + 4];
                af[i][3] = As32[m0 + 8 * 36 + kw + 4];
            }
            uint32_t bf[8][2];
#pragma unroll
            for (int j = 0; j < 8; j++) {
                int n0 = (warpN + 8 * j + g) * 36;
                bf[j][0] = Bs32[n0 + kw];
                bf[j][1] = Bs32[n0 + kw + 4];
            }
#pragma unroll
            for (int i = 0; i < 4; i++)
#pragma unroll
                for (int j = 0; j < 8; j++)
                    mma_f16(acc[i][j], af[i], bf[j]);
        }

        const int kn = ki + NSTAGE - 1;
        if (kn < NK) load_stage(kn & 3, kn);
        asm volatile("cp.async.commit_group;" ::: "memory");
    }

    // Epilogue: bias + store (fp32)
#pragma unroll
    for (int i = 0; i < 4; i++) {
        int row0 = bm + warpM + 16 * i + g;
#pragma unroll
        for (int j = 0; j < 8; j++) {
            int col = bn + warpN + 8 * j + 2 * tig;
            float2 bi = *reinterpret_cast<const float2*>(&bias[col]);
            float2 v0 = make_float2(acc[i][j][0] + bi.x, acc[i][j][1] + bi.y);
            float2 v1 = make_float2(acc[i][j][2] + bi.x, acc[i][j][3] + bi.y);
            *reinterpret_cast<float2*>(&Z[(size_t)row0 * H_SZ + col]) = v0;
            *reinterpret_cast<float2*>(&Z[(size_t)(row0 + 8) * H_SZ + col]) = v1;
        }
    }
}

// ===========================================================================
// Mixed activation (R8-validated structure): E cached from reduction phase;
// relu/lrelu merged; tanh&sigmoid share one tanh.approx; gelu exact.
// Writes h as fp16. Fused mask pass-through (fp32).
// ===========================================================================
__global__ __launch_bounds__(256)
void act_kernel(const float* __restrict__ Z, const int* __restrict__ tids,
                const float* __restrict__ mask, __half* __restrict__ Hout,
                float* __restrict__ MOut)
{
    const int row  = blockIdx.x;
    const int t    = threadIdx.x;
    const int lane = t & 31, wid = t >> 5;
    const size_t base = (size_t)row * H_SZ;

    float4 z4 = *reinterpret_cast<const float4*>(Z + base + t * 4);
    int4  i4 = *reinterpret_cast<const int4*>(tids + t * 4);
    float zr[4] = {z4.x, z4.y, z4.z, z4.w};
    int   tr[4] = {i4.x, i4.y, i4.z, i4.w};

    float E[4];
    float s3 = 0.f, s4 = 0.f;
#pragma unroll
    for (int q = 0; q < 4; q++) {
        bool p3 = (tr[q] == 3), p4 = (tr[q] == 4);
        float sg = p4 ? -zr[q] : zr[q];
        E[q] = __expf(sg);
        s3 += p3 ? E[q] : 0.f;
        s4 += p4 ? E[q] : 0.f;
    }
#pragma unroll
    for (int off = 16; off; off >>= 1) {
        s3 += __shfl_xor_sync(0xffffffffu, s3, off);
        s4 += __shfl_xor_sync(0xffffffffu, s4, off);
    }
    __shared__ float sC[8], sD[8];
    if (lane == 0) { sC[wid] = s3; sD[wid] = s4; }
    __syncthreads();
    s3 = 0.f; s4 = 0.f;
#pragma unroll
    for (int j = 0; j < 8; j++) { s3 += sC[j]; s4 += sD[j]; }
    float r3 = __frcp_rn(s3), r4 = __frcp_rn(s4);

    float4 mk = *reinterpret_cast<const float4*>(mask + base + t * 4);
    float mv[4] = {mk.x, mk.y, mk.z, mk.w};
    float ov[4];
#pragma unroll
    for (int q = 0; q < 4; q++) {
        float x = zr[q];
        int  ty = tr[q];
        float cmin  = (ty == 6) ? LRELU_SLOPE : 0.f;
        float vrelu = fmaxf(x, 0.f) + cmin * fminf(x, 0.f);
        float targ  = (ty == 2) ? 0.5f * x : x;
        float th    = tanh_fast(targ);
        float vtanh = (ty == 2) ? fmaf(0.5f, th, 0.5f) : th;
        float vsoft = E[q] * ((ty == 3) ? r3 : r4);
        float v = (ty <= 0) ? vrelu
                : (ty <= 2) ? vtanh
                : (ty <= 4) ? vsoft
                : vrelu;
        if (ty == 5) v = x * normcdff(x);
        ov[q] = v * mv[q] * KEEP_SCALE;
    }
    __half2 h01 = __floats2half2_rn(ov[0], ov[1]);
    __half2 h23 = __floats2half2_rn(ov[2], ov[3]);
    *reinterpret_cast<uint2*>(Hout + base + t * 4) =
        make_uint2(*(uint32_t*)&h01, *(uint32_t*)&h23);
    *reinterpret_cast<float4*>(MOut + base + t * 4) = mk;
}

// ===========================================================================
// Layer 3 + log_softmax (R8-validated structure, fp16 Hm).
// Warp handles 8 rows; W3 fragments hoisted per j-chunk, reused across rows.
// ===========================================================================
__global__ __launch_bounds__(256)
void layer3_kernel(const __half* __restrict__ Hm, const float* __restrict__ W3,
                   const float* __restrict__ b3, float* __restrict__ Out)
{
    __shared__ float Ws[C_SZ * H_SZ];
    __shared__ float bs[16];
    for (int i = threadIdx.x; i < C_SZ * H_SZ; i += 256) Ws[i] = W3[i];
    if (threadIdx.x < C_SZ) bs[threadIdx.x] = b3[threadIdx.x];
    __syncthreads();

    const int warp = threadIdx.x >> 5;
    const int lane = threadIdx.x & 31;
    const int row0 = blockIdx.x * 64 + warp * 8;   // 8 rows per warp
    const float4* Ws4 = reinterpret_cast<const float4*>(Ws);

    float acc[8][C_SZ];
#pragma unroll
    for (int r = 0; r < 8; r++)
#pragma unroll
        for (int c = 0; c < C_SZ; c++) acc[r][c] = 0.f;

#pragma unroll
    for (int j = 0; j < 8; j++) {
        int idx = lane + 32 * j;
        float4 wv[C_SZ];
#pragma unroll
        for (int c = 0; c < C_SZ; c++) wv[c] = Ws4[c * 256 + idx];
#pragma unroll
        for (int r = 0; r < 8; r++) {
            uint2 hraw = *reinterpret_cast<const uint2*>(
                &Hm[(size_t)(row0 + r) * H_SZ + idx * 4]);
            float2 h01 = __half22float2(*(__half2*)&hraw.x);
            float2 h23 = __half22float2(*(__half2*)&hraw.y);
#pragma unroll
            for (int c = 0; c < C_SZ; c++)
                acc[r][c] += h01.x * wv[c].x + h01.y * wv[c].y
                           + h23.x * wv[c].z + h23.y * wv[c].w;
        }
    }

#pragma unroll
    for (int r = 0; r < 8; r++) {
#pragma unroll
        for (int c = 0; c < C_SZ; c++)
#pragma unroll
            for (int off = 16; off; off >>= 1)
                acc[r][c] += __shfl_xor_sync(0xffffffff, acc[r][c], off);

        if (lane == 0) {
            float l[C_SZ], mx = -INFINITY;
#pragma unroll
            for (int c = 0; c < C_SZ; c++) {
                l[c] = acc[r][c] + bs[c];
                mx = fmaxf(mx, l[c]);
            }
            float s = 0.f;
#pragma unroll
            for (int c = 0; c < C_SZ; c++) s += __expf(l[c] - mx);
            float lse = mx + __logf(s);
#pragma unroll
            for (int c = 0; c < C_SZ; c++)
                Out[(size_t)(row0 + r) * C_SZ + c] = l[c] - lse;
        }
    }
}

// ===========================================================================
extern "C" void kernel_launch(void* const* d_in, const int* in_sizes, int n_in,
                              void* d_out, int out_size)
{
    (void)in_sizes; (void)n_in; (void)out_size;
    const float* x    = (const float*)d_in[0];
    const float* W0   = (const float*)d_in[1];
    const float* b0   = (const float*)d_in[2];
    const float* W1   = (const float*)d_in[3];
    const float* b1   = (const float*)d_in[4];
    const float* W2   = (const float*)d_in[5];
    const float* b2   = (const float*)d_in[6];
    const float* W3   = (const float*)d_in[7];
    const float* b3   = (const float*)d_in[8];
    const float* m1   = (const float*)d_in[9];
    const float* m2   = (const float*)d_in[10];
    const float* m3   = (const float*)d_in[11];
    const int*   tids = (const int*)d_in[12];
    float* out = (float*)d_out;

    float  *z;
    __half *h, *xh, *w0h, *w1h, *w2h;
    cudaGetSymbolAddress((void**)&z,  g_z);
    cudaGetSymbolAddress((void**)&h,  g_h);
    cudaGetSymbolAddress((void**)&xh, g_xh);
    cudaGetSymbolAddress((void**)&w0h, g_w0);
    cudaGetSymbolAddress((void**)&w1h, g_w1);
    cudaGetSymbolAddress((void**)&w2h, g_w2);

    cudaFuncSetAttribute(gemm_f16_nt<D_IN>,
                         cudaFuncAttributeMaxDynamicSharedMemorySize, GEMM_SMEM);
    cudaFuncSetAttribute(gemm_f16_nt<H_SZ>,
                         cudaFuncAttributeMaxDynamicSharedMemorySize, GEMM_SMEM);

    // Convert inputs/weights to fp16
    cvt_f2h<<<(B_SZ * D_IN) / 1024, 256>>>(x, xh);
    cvt_f2h<<<(H_SZ * D_IN) / 1024, 256>>>(W0, w0h);
    cvt_f2h<<<(H_SZ * H_SZ) / 1024, 256>>>(W1, w1h);
    cvt_f2h<<<(H_SZ * H_SZ) / 1024, 256>>>(W2, w2h);

    dim3 grid(H_SZ / BN, B_SZ / BM);   // (4, 256)
    float* mout = out + (size_t)B_SZ * C_SZ;
    size_t BH = (size_t)B_SZ * H_SZ;

    gemm_f16_nt<D_IN><<<grid, 256, GEMM_SMEM>>>(xh, w0h, b0, z);
    act_kernel<<<B_SZ, 256>>>(z, tids, m1, h, mout);

    gemm_f16_nt<H_SZ><<<grid, 256, GEMM_SMEM>>>(h, w1h, b1, z);
    act_kernel<<<B_SZ, 256>>>(z, tids + H_SZ, m2, h, mout + BH);

    gemm_f16_nt<H_SZ><<<grid, 256, GEMM_SMEM>>>(h, w2h, b2, z);
    act_kernel<<<B_SZ, 256>>>(z, tids + 2 * H_SZ, m3, h, mout + 2 * BH);

    layer3_kernel<<<B_SZ / 64, 256>>>(h, W3, b3, out);
}

// round 14
// speedup vs baseline: 2.7073x; 1.0128x over previous
#include <cuda_runtime.h>
#include <cuda_fp16.h>
#include <math.h>
#include <stdint.h>

#define B_SZ 32768
#define H_SZ 1024
#define D_IN 784
#define C_SZ 10
#define KEEP_SCALE 2.0f
#define LRELU_SLOPE 0.01f

// Scratch (device globals — allocation is forbidden)
__device__ float  g_z[(size_t)B_SZ * H_SZ];        // pre-activation (fp32)
__device__ __half g_h[(size_t)B_SZ * H_SZ];        // activations (fp16)
__device__ __half g_xh[(size_t)B_SZ * D_IN];       // x converted to fp16
__device__ __half g_w0[(size_t)H_SZ * D_IN];       // W0 fp16
__device__ __half g_w1[(size_t)H_SZ * H_SZ];       // W1 fp16
__device__ __half g_w2[(size_t)H_SZ * H_SZ];       // W2 fp16

// ===========================================================================
// Helpers
// ===========================================================================
__device__ __forceinline__ uint32_t smem_u32(const void* p) {
    uint32_t a;
    asm("{ .reg .u64 t; cvta.to.shared.u64 t, %1; cvt.u32.u64 %0, t; }"
        : "=r"(a) : "l"(p));
    return a;
}

__device__ __forceinline__ void cp_async16(uint32_t dst, const void* src, int src_bytes) {
    asm volatile("cp.async.cg.shared.global [%0], [%1], 16, %2;"
                 :: "r"(dst), "l"(src), "r"(src_bytes) : "memory");
}

__device__ __forceinline__ float tanh_fast(float x) {
    float r;
    asm("tanh.approx.f32 %0, %1;" : "=f"(r) : "f"(x));
    return r;
}

#define LDSM_X4(r0, r1, r2, r3, addr) \
    asm volatile("ldmatrix.sync.aligned.m8n8.x4.shared.b16 {%0,%1,%2,%3}, [%4];" \
                 : "=r"(r0), "=r"(r1), "=r"(r2), "=r"(r3) : "r"(addr))

__device__ __forceinline__ void mma_f16(float* d, const uint32_t* a, const uint32_t* b) {
    asm volatile(
        "mma.sync.aligned.m16n8k16.row.col.f32.f16.f16.f32 "
        "{%0,%1,%2,%3}, {%4,%5,%6,%7}, {%8,%9}, {%0,%1,%2,%3};"
        : "+f"(d[0]), "+f"(d[1]), "+f"(d[2]), "+f"(d[3])
        : "r"(a[0]), "r"(a[1]), "r"(a[2]), "r"(a[3]), "r"(b[0]), "r"(b[1]));
}

// ===========================================================================
// fp32 -> fp16 conversion (vectorized, n multiple of 1024)
// ===========================================================================
__global__ __launch_bounds__(256)
void cvt_f2h(const float* __restrict__ src, __half* __restrict__ dst) {
    size_t i = ((size_t)blockIdx.x * 256 + threadIdx.x) * 4;
    float4 v = *reinterpret_cast<const float4*>(src + i);
    __half2 h01 = __floats2half2_rn(v.x, v.y);
    __half2 h23 = __floats2half2_rn(v.z, v.w);
    uint2 o = make_uint2(*(uint32_t*)&h01, *(uint32_t*)&h23);
    *reinterpret_cast<uint2*>(dst + i) = o;
}

// ===========================================================================
// fp16 mma.sync GEMM: Z[m,n] = sum_k A[m,k]*W[n,k] + bias[n]  (fp32 out)
// CTA 128x256, BK=64 halves, 256 threads (8 warps 2x4, warp tile 64x64).
// Fragments via ldmatrix.x4 (4x fewer smem load instructions).
// Smem m-major rows of 72 halves; 4-stage cp.async pipeline with zfill tail.
// ===========================================================================
#define BM 128
#define BN 256
#define BK 64                                   // halves
#define PADH 72                                 // halves per row (36 words)
#define NSTAGE 4
#define STG_HALVES ((BM + BN) * PADH)           // 27648 halves = 55296 B
#define GEMM_SMEM (NSTAGE * STG_HALVES * 2)     // 221184 bytes

template <int K>
__global__ __launch_bounds__(256, 1)
void gemm_f16_nt(const __half* __restrict__ A, const __half* __restrict__ W,
                 const float* __restrict__ bias, float* __restrict__ Z)
{
    constexpr int NK = (K + BK - 1) / BK;

    extern __shared__ __align__(16) __half sm[];

    const int tid  = threadIdx.x;
    const int wid  = tid >> 5;
    const int lane = tid & 31;
    const int warpM = (wid & 1) * 64;       // 2 warp-rows
    const int warpN = (wid >> 1) * 64;      // 4 warp-cols
    const int bm = blockIdx.y * BM;
    const int bn = blockIdx.x * BN;

    const __half* Ag = A + (size_t)bm * K;
    const __half* Wg = W + (size_t)bn * K;

    const uint32_t sm_u = smem_u32(sm);
    // ldmatrix per-lane byte offsets (within a stage)
    const uint32_t aoff = 2u * ((warpM + (lane & 15)) * PADH + ((lane >> 4) << 3));
    const uint32_t boff = 2u * (BM * PADH
                        + (warpN + ((lane >> 4) << 3) + (lane & 7)) * PADH
                        + (((lane >> 3) & 1) << 3));

    float acc[4][8][4];
#pragma unroll
    for (int i = 0; i < 4; i++)
#pragma unroll
        for (int j = 0; j < 8; j++)
#pragma unroll
            for (int q = 0; q < 4; q++) acc[i][j][q] = 0.f;

    auto load_stage = [&](int s, int kc) {
        const int k0 = kc * BK;
        __half* As = sm + s * STG_HALVES;
        __half* Bs = As + BM * PADH;
#pragma unroll
        for (int it = 0; it < 4; it++) {
            int idx = tid + it * 256;
            int row = idx >> 3, q = idx & 7;
            int gk  = k0 + q * 8;
            int sb  = (K % BK == 0) ? 16 : ((gk < K) ? 16 : 0);
            int gkc = (K % BK == 0) ? gk : min(gk, K - 8);
            cp_async16(smem_u32(&As[row * PADH + q * 8]),
                       Ag + (size_t)row * K + gkc, sb);
        }
#pragma unroll
        for (int it = 0; it < 8; it++) {
            int idx = tid + it * 256;
            int row = idx >> 3, q = idx & 7;
            int gk  = k0 + q * 8;
            int sb  = (K % BK == 0) ? 16 : ((gk < K) ? 16 : 0);
            int gkc = (K % BK == 0) ? gk : min(gk, K - 8);
            cp_async16(smem_u32(&Bs[row * PADH + q * 8]),
                       Wg + (size_t)row * K + gkc, sb);
        }
    };

    // Prologue
#pragma unroll
    for (int s = 0; s < NSTAGE - 1; s++) {
        load_stage(s, s);
        asm volatile("cp.async.commit_group;" ::: "memory");
    }

#pragma unroll 1
    for (int ki = 0; ki < NK; ki++) {
        asm volatile("cp.async.wait_group 2;" ::: "memory");
        __syncthreads();

        const uint32_t stg = sm_u + (uint32_t)((ki & 3) * STG_HALVES * 2);
        const uint32_t aBase = stg + aoff;
        const uint32_t bBase = stg + boff;

#pragma unroll
        for (int ks = 0; ks < 4; ks++) {          // 4 k16-steps per BK=64
            const uint32_t kd = ks * 32;          // 16 halves = 32 bytes

            uint32_t af[4][4];
#pragma unroll
            for (int i = 0; i < 4; i++)
                LDSM_X4(af[i][0], af[i][1], af[i][2], af[i][3],
                        aBase + i * (16 * PADH * 2) + kd);
            uint32_t bf[8][2];
#pragma unroll
            for (int jp = 0; jp < 4; jp++)
                LDSM_X4(bf[2 * jp][0], bf[2 * jp][1],
                        bf[2 * jp + 1][0], bf[2 * jp + 1][1],
                        bBase + jp * (16 * PADH * 2) + kd);
#pragma unroll
            for (int i = 0; i < 4; i++)
#pragma unroll
                for (int j = 0; j < 8; j++)
                    mma_f16(acc[i][j], af[i], bf[j]);
        }

        const int kn = ki + NSTAGE - 1;
        if (kn < NK) load_stage(kn & 3, kn);
        asm volatile("cp.async.commit_group;" ::: "memory");
    }

    // Epilogue: bias + store (fp32)
    const int g   = lane >> 2;
    const int tig = lane & 3;
#pragma unroll
    for (int i = 0; i < 4; i++) {
        int row0 = bm + warpM + 16 * i + g;
#pragma unroll
        for (int j = 0; j < 8; j++) {
            int col = bn + warpN + 8 * j + 2 * tig;
            float2 bi = *reinterpret_cast<const float2*>(&bias[col]);
            float2 v0 = make_float2(acc[i][j][0] + bi.x, acc[i][j][1] + bi.y);
            float2 v1 = make_float2(acc[i][j][2] + bi.x, acc[i][j][3] + bi.y);
            *reinterpret_cast<float2*>(&Z[(size_t)row0 * H_SZ + col]) = v0;
            *reinterpret_cast<float2*>(&Z[(size_t)(row0 + 8) * H_SZ + col]) = v1;
        }
    }
}

// ===========================================================================
// Mixed activation (R8-validated structure): E cached from reduction phase;
// relu/lrelu merged; tanh&sigmoid share one tanh.approx; gelu exact.
// Writes h as fp16. Fused mask pass-through (fp32).
// ===========================================================================
__global__ __launch_bounds__(256)
void act_kernel(const float* __restrict__ Z, const int* __restrict__ tids,
                const float* __restrict__ mask, __half* __restrict__ Hout,
                float* __restrict__ MOut)
{
    const int row  = blockIdx.x;
    const int t    = threadIdx.x;
    const int lane = t & 31, wid = t >> 5;
    const size_t base = (size_t)row * H_SZ;

    float4 z4 = *reinterpret_cast<const float4*>(Z + base + t * 4);
    int4  i4 = *reinterpret_cast<const int4*>(tids + t * 4);
    float zr[4] = {z4.x, z4.y, z4.z, z4.w};
    int   tr[4] = {i4.x, i4.y, i4.z, i4.w};

    float E[4];
    float s3 = 0.f, s4 = 0.f;
#pragma unroll
    for (int q = 0; q < 4; q++) {
        bool p3 = (tr[q] == 3), p4 = (tr[q] == 4);
        float sg = p4 ? -zr[q] : zr[q];
        E[q] = __expf(sg);
        s3 += p3 ? E[q] : 0.f;
        s4 += p4 ? E[q] : 0.f;
    }
#pragma unroll
    for (int off = 16; off; off >>= 1) {
        s3 += __shfl_xor_sync(0xffffffffu, s3, off);
        s4 += __shfl_xor_sync(0xffffffffu, s4, off);
    }
    __shared__ float sC[8], sD[8];
    if (lane == 0) { sC[wid] = s3; sD[wid] = s4; }
    __syncthreads();
    s3 = 0.f; s4 = 0.f;
#pragma unroll
    for (int j = 0; j < 8; j++) { s3 += sC[j]; s4 += sD[j]; }
    float r3 = __frcp_rn(s3), r4 = __frcp_rn(s4);

    float4 mk = *reinterpret_cast<const float4*>(mask + base + t * 4);
    float mv[4] = {mk.x, mk.y, mk.z, mk.w};
    float ov[4];
#pragma unroll
    for (int q = 0; q < 4; q++) {
        float x = zr[q];
        int  ty = tr[q];
        float cmin  = (ty == 6) ? LRELU_SLOPE : 0.f;
        float vrelu = fmaxf(x, 0.f) + cmin * fminf(x, 0.f);
        float targ  = (ty == 2) ? 0.5f * x : x;
        float th    = tanh_fast(targ);
        float vtanh = (ty == 2) ? fmaf(0.5f, th, 0.5f) : th;
        float vsoft = E[q] * ((ty == 3) ? r3 : r4);
        float v = (ty <= 0) ? vrelu
                : (ty <= 2) ? vtanh
                : (ty <= 4) ? vsoft
                : vrelu;
        if (ty == 5) v = x * normcdff(x);
        ov[q] = v * mv[q] * KEEP_SCALE;
    }
    __half2 h01 = __floats2half2_rn(ov[0], ov[1]);
    __half2 h23 = __floats2half2_rn(ov[2], ov[3]);
    *reinterpret_cast<uint2*>(Hout + base + t * 4) =
        make_uint2(*(uint32_t*)&h01, *(uint32_t*)&h23);
    *reinterpret_cast<float4*>(MOut + base + t * 4) = mk;
}

// ===========================================================================
// Layer 3 + log_softmax (R8-validated structure, fp16 Hm).
// ===========================================================================
__global__ __launch_bounds__(256)
void layer3_kernel(const __half* __restrict__ Hm, const float* __restrict__ W3,
                   const float* __restrict__ b3, float* __restrict__ Out)
{
    __shared__ float Ws[C_SZ * H_SZ];
    __shared__ float bs[16];
    for (int i = threadIdx.x; i < C_SZ * H_SZ; i += 256) Ws[i] = W3[i];
    if (threadIdx.x < C_SZ) bs[threadIdx.x] = b3[threadIdx.x];
    __syncthreads();

    const int warp = threadIdx.x >> 5;
    const int lane = threadIdx.x & 31;
    const int row0 = blockIdx.x * 64 + warp * 8;   // 8 rows per warp
    const float4* Ws4 = reinterpret_cast<const float4*>(Ws);

    float acc[8][C_SZ];
#pragma unroll
    for (int r = 0; r < 8; r++)
#pragma unroll
        for (int c = 0; c < C_SZ; c++) acc[r][c] = 0.f;

#pragma unroll
    for (int j = 0; j < 8; j++) {
        int idx = lane + 32 * j;
        float4 wv[C_SZ];
#pragma unroll
        for (int c = 0; c < C_SZ; c++) wv[c] = Ws4[c * 256 + idx];
#pragma unroll
        for (int r = 0; r < 8; r++) {
            uint2 hraw = *reinterpret_cast<const uint2*>(
                &Hm[(size_t)(row0 + r) * H_SZ + idx * 4]);
            float2 h01 = __half22float2(*(__half2*)&hraw.x);
            float2 h23 = __half22float2(*(__half2*)&hraw.y);
#pragma unroll
            for (int c = 0; c < C_SZ; c++)
                acc[r][c] += h01.x * wv[c].x + h01.y * wv[c].y
                           + h23.x * wv[c].z + h23.y * wv[c].w;
        }
    }

#pragma unroll
    for (int r = 0; r < 8; r++) {
#pragma unroll
        for (int c = 0; c < C_SZ; c++)
#pragma unroll
            for (int off = 16; off; off >>= 1)
                acc[r][c] += __shfl_xor_sync(0xffffffff, acc[r][c], off);

        if (lane == 0) {
            float l[C_SZ], mx = -INFINITY;
#pragma unroll
            for (int c = 0; c < C_SZ; c++) {
                l[c] = acc[r][c] + bs[c];
                mx = fmaxf(mx, l[c]);
            }
            float s = 0.f;
#pragma unroll
            for (int c = 0; c < C_SZ; c++) s += __expf(l[c] - mx);
            float lse = mx + __logf(s);
#pragma unroll
            for (int c = 0; c < C_SZ; c++)
                Out[(size_t)(row0 + r) * C_SZ + c] = l[c] - lse;
        }
    }
}

// ===========================================================================
extern "C" void kernel_launch(void* const* d_in, const int* in_sizes, int n_in,
                              void* d_out, int out_size)
{
    (void)in_sizes; (void)n_in; (void)out_size;
    const float* x    = (const float*)d_in[0];
    const float* W0   = (const float*)d_in[1];
    const float* b0   = (const float*)d_in[2];
    const float* W1   = (const float*)d_in[3];
    const float* b1   = (const float*)d_in[4];
    const float* W2   = (const float*)d_in[5];
    const float* b2   = (const float*)d_in[6];
    const float* W3   = (const float*)d_in[7];
    const float* b3   = (const float*)d_in[8];
    const float* m1   = (const float*)d_in[9];
    const float* m2   = (const float*)d_in[10];
    const float* m3   = (const float*)d_in[11];
    const int*   tids = (const int*)d_in[12];
    float* out = (float*)d_out;

    float  *z;
    __half *h, *xh, *w0h, *w1h, *w2h;
    cudaGetSymbolAddress((void**)&z,  g_z);
    cudaGetSymbolAddress((void**)&h,  g_h);
    cudaGetSymbolAddress((void**)&xh, g_xh);
    cudaGetSymbolAddress((void**)&w0h, g_w0);
    cudaGetSymbolAddress((void**)&w1h, g_w1);
    cudaGetSymbolAddress((void**)&w2h, g_w2);

    cudaFuncSetAttribute(gemm_f16_nt<D_IN>,
                         cudaFuncAttributeMaxDynamicSharedMemorySize, GEMM_SMEM);
    cudaFuncSetAttribute(gemm_f16_nt<H_SZ>,
                         cudaFuncAttributeMaxDynamicSharedMemorySize, GEMM_SMEM);

    // Convert inputs/weights to fp16
    cvt_f2h<<<(B_SZ * D_IN) / 1024, 256>>>(x, xh);
    cvt_f2h<<<(H_SZ * D_IN) / 1024, 256>>>(W0, w0h);
    cvt_f2h<<<(H_SZ * H_SZ) / 1024, 256>>>(W1, w1h);
    cvt_f2h<<<(H_SZ * H_SZ) / 1024, 256>>>(W2, w2h);

    dim3 grid(H_SZ / BN, B_SZ / BM);   // (4, 256)
    float* mout = out + (size_t)B_SZ * C_SZ;
    size_t BH = (size_t)B_SZ * H_SZ;

    gemm_f16_nt<D_IN><<<grid, 256, GEMM_SMEM>>>(xh, w0h, b0, z);
    act_kernel<<<B_SZ, 256>>>(z, tids, m1, h, mout);

    gemm_f16_nt<H_SZ><<<grid, 256, GEMM_SMEM>>>(h, w1h, b1, z);
    act_kernel<<<B_SZ, 256>>>(z, tids + H_SZ, m2, h, mout + BH);

    gemm_f16_nt<H_SZ><<<grid, 256, GEMM_SMEM>>>(h, w2h, b2, z);
    act_kernel<<<B_SZ, 256>>>(z, tids + 2 * H_SZ, m3, h, mout + 2 * BH);

    layer3_kernel<<<B_SZ / 64, 256>>>(h, W3, b3, out);
}

// round 15
// speedup vs baseline: 2.7116x; 1.0016x over previous
#include <cuda_runtime.h>
#include <cuda_fp16.h>
#include <math.h>
#include <stdint.h>

#define B_SZ 32768
#define H_SZ 1024
#define D_IN 784
#define C_SZ 10
#define KEEP_SCALE 2.0f
#define LRELU_SLOPE 0.01f

// Scratch (device globals — allocation is forbidden)
__device__ __half g_z[(size_t)B_SZ * H_SZ];        // pre-activation (fp16)
__device__ __half g_h[(size_t)B_SZ * H_SZ];        // activations (fp16)
__device__ __half g_xh[(size_t)B_SZ * D_IN];       // x converted to fp16
__device__ __half g_w0[(size_t)H_SZ * D_IN];       // W0 fp16
__device__ __half g_w1[(size_t)H_SZ * H_SZ];       // W1 fp16
__device__ __half g_w2[(size_t)H_SZ * H_SZ];       // W2 fp16

// ===========================================================================
// Helpers
// ===========================================================================
__device__ __forceinline__ uint32_t smem_u32(const void* p) {
    uint32_t a;
    asm("{ .reg .u64 t; cvta.to.shared.u64 t, %1; cvt.u32.u64 %0, t; }"
        : "=r"(a) : "l"(p));
    return a;
}

__device__ __forceinline__ void cp_async16(uint32_t dst, const void* src, int src_bytes) {
    asm volatile("cp.async.cg.shared.global [%0], [%1], 16, %2;"
                 :: "r"(dst), "l"(src), "r"(src_bytes) : "memory");
}

__device__ __forceinline__ float tanh_fast(float x) {
    float r;
    asm("tanh.approx.f32 %0, %1;" : "=f"(r) : "f"(x));
    return r;
}

#define LDSM_X4(r0, r1, r2, r3, addr) \
    asm volatile("ldmatrix.sync.aligned.m8n8.x4.shared.b16 {%0,%1,%2,%3}, [%4];" \
                 : "=r"(r0), "=r"(r1), "=r"(r2), "=r"(r3) : "r"(addr))

__device__ __forceinline__ void mma_f16(float* d, const uint32_t* a, const uint32_t* b) {
    asm volatile(
        "mma.sync.aligned.m16n8k16.row.col.f32.f16.f16.f32 "
        "{%0,%1,%2,%3}, {%4,%5,%6,%7}, {%8,%9}, {%0,%1,%2,%3};"
        : "+f"(d[0]), "+f"(d[1]), "+f"(d[2]), "+f"(d[3])
        : "r"(a[0]), "r"(a[1]), "r"(a[2]), "r"(a[3]), "r"(b[0]), "r"(b[1]));
}

// ===========================================================================
// Fused fp32 -> fp16 conversion for x, W0, W1, W2 in ONE launch.
// Each block converts 1024 elements.
// ===========================================================================
#define NB_X  ((B_SZ * D_IN) / 1024)             // 25088
#define NB_W0 ((H_SZ * D_IN) / 1024)             // 784
#define NB_W  ((H_SZ * H_SZ) / 1024)             // 1024
#define NB_TOTAL (NB_X + NB_W0 + 2 * NB_W)       // 27920

__global__ __launch_bounds__(256)
void cvt_all(const float* __restrict__ x,  __half* __restrict__ xh,
             const float* __restrict__ w0, __half* __restrict__ w0h,
             const float* __restrict__ w1, __half* __restrict__ w1h,
             const float* __restrict__ w2, __half* __restrict__ w2h)
{
    int b = blockIdx.x;
    const float* src; __half* dst; size_t off;
    if (b < NB_X)                       { src = x;  dst = xh;  off = (size_t)b; }
    else if (b < NB_X + NB_W0)          { src = w0; dst = w0h; off = (size_t)(b - NB_X); }
    else if (b < NB_X + NB_W0 + NB_W)   { src = w1; dst = w1h; off = (size_t)(b - NB_X - NB_W0); }
    else                                { src = w2; dst = w2h; off = (size_t)(b - NB_X - NB_W0 - NB_W); }
    size_t i = (off * 1024) + (size_t)threadIdx.x * 4;
    float4 v = *reinterpret_cast<const float4*>(src + i);
    __half2 h01 = __floats2half2_rn(v.x, v.y);
    __half2 h23 = __floats2half2_rn(v.z, v.w);
    *reinterpret_cast<uint2*>(dst + i) =
        make_uint2(*(uint32_t*)&h01, *(uint32_t*)&h23);
}

// ===========================================================================
// fp16 mma.sync GEMM: Z[m,n] = sum_k A[m,k]*W[n,k] + bias[n]  (fp16 out)
// CTA 128x256, BK=64 halves, 256 threads (8 warps 2x4, warp tile 64x64).
// Fragments via ldmatrix.x4. 4-stage cp.async pipeline with zfill tail.
// ===========================================================================
#define BM 128
#define BN 256
#define BK 64                                   // halves
#define PADH 72                                 // halves per row (36 words)
#define NSTAGE 4
#define STG_HALVES ((BM + BN) * PADH)           // 27648 halves = 55296 B
#define GEMM_SMEM (NSTAGE * STG_HALVES * 2)     // 221184 bytes

template <int K>
__global__ __launch_bounds__(256, 1)
void gemm_f16_nt(const __half* __restrict__ A, const __half* __restrict__ W,
                 const float* __restrict__ bias, __half* __restrict__ Z)
{
    constexpr int NK = (K + BK - 1) / BK;

    extern __shared__ __align__(16) __half sm[];

    const int tid  = threadIdx.x;
    const int wid  = tid >> 5;
    const int lane = tid & 31;
    const int warpM = (wid & 1) * 64;       // 2 warp-rows
    const int warpN = (wid >> 1) * 64;      // 4 warp-cols
    const int bm = blockIdx.y * BM;
    const int bn = blockIdx.x * BN;

    const __half* Ag = A + (size_t)bm * K;
    const __half* Wg = W + (size_t)bn * K;

    const uint32_t sm_u = smem_u32(sm);
    const uint32_t aoff = 2u * ((warpM + (lane & 15)) * PADH + ((lane >> 4) << 3));
    const uint32_t boff = 2u * (BM * PADH
                        + (warpN + ((lane >> 4) << 3) + (lane & 7)) * PADH
                        + (((lane >> 3) & 1) << 3));

    float acc[4][8][4];
#pragma unroll
    for (int i = 0; i < 4; i++)
#pragma unroll
        for (int j = 0; j < 8; j++)
#pragma unroll
            for (int q = 0; q < 4; q++) acc[i][j][q] = 0.f;

    auto load_stage = [&](int s, int kc) {
        const int k0 = kc * BK;
        __half* As = sm + s * STG_HALVES;
        __half* Bs = As + BM * PADH;
#pragma unroll
        for (int it = 0; it < 4; it++) {
            int idx = tid + it * 256;
            int row = idx >> 3, q = idx & 7;
            int gk  = k0 + q * 8;
            int sb  = (K % BK == 0) ? 16 : ((gk < K) ? 16 : 0);
            int gkc = (K % BK == 0) ? gk : min(gk, K - 8);
            cp_async16(smem_u32(&As[row * PADH + q * 8]),
                       Ag + (size_t)row * K + gkc, sb);
        }
#pragma unroll
        for (int it = 0; it < 8; it++) {
            int idx = tid + it * 256;
            int row = idx >> 3, q = idx & 7;
            int gk  = k0 + q * 8;
            int sb  = (K % BK == 0) ? 16 : ((gk < K) ? 16 : 0);
            int gkc = (K % BK == 0) ? gk : min(gk, K - 8);
            cp_async16(smem_u32(&Bs[row * PADH + q * 8]),
                       Wg + (size_t)row * K + gkc, sb);
        }
    };

    // Prologue
#pragma unroll
    for (int s = 0; s < NSTAGE - 1; s++) {
        load_stage(s, s);
        asm volatile("cp.async.commit_group;" ::: "memory");
    }

#pragma unroll 1
    for (int ki = 0; ki < NK; ki++) {
        asm volatile("cp.async.wait_group 2;" ::: "memory");
        __syncthreads();

        const uint32_t stg = sm_u + (uint32_t)((ki & 3) * STG_HALVES * 2);
        const uint32_t aBase = stg + aoff;
        const uint32_t bBase = stg + boff;

#pragma unroll
        for (int ks = 0; ks < 4; ks++) {
            const uint32_t kd = ks * 32;

            uint32_t af[4][4];
#pragma unroll
            for (int i = 0; i < 4; i++)
                LDSM_X4(af[i][0], af[i][1], af[i][2], af[i][3],
                        aBase + i * (16 * PADH * 2) + kd);
            uint32_t bf[8][2];
#pragma unroll
            for (int jp = 0; jp < 4; jp++)
                LDSM_X4(bf[2 * jp][0], bf[2 * jp][1],
                        bf[2 * jp + 1][0], bf[2 * jp + 1][1],
                        bBase + jp * (16 * PADH * 2) + kd);
#pragma unroll
            for (int i = 0; i < 4; i++)
#pragma unroll
                for (int j = 0; j < 8; j++)
                    mma_f16(acc[i][j], af[i], bf[j]);
        }

        const int kn = ki + NSTAGE - 1;
        if (kn < NK) load_stage(kn & 3, kn);
        asm volatile("cp.async.commit_group;" ::: "memory");
    }

    // Epilogue: bias + store (fp16)
    const int g   = lane >> 2;
    const int tig = lane & 3;
#pragma unroll
    for (int i = 0; i < 4; i++) {
        int row0 = bm + warpM + 16 * i + g;
#pragma unroll
        for (int j = 0; j < 8; j++) {
            int col = bn + warpN + 8 * j + 2 * tig;
            float2 bi = *reinterpret_cast<const float2*>(&bias[col]);
            __half2 v0 = __floats2half2_rn(acc[i][j][0] + bi.x, acc[i][j][1] + bi.y);
            __half2 v1 = __floats2half2_rn(acc[i][j][2] + bi.x, acc[i][j][3] + bi.y);
            *reinterpret_cast<__half2*>(&Z[(size_t)row0 * H_SZ + col]) = v0;
            *reinterpret_cast<__half2*>(&Z[(size_t)(row0 + 8) * H_SZ + col]) = v1;
        }
    }
}

// ===========================================================================
// Mixed activation (R8-validated structure, fp16 z input): E cached from
// reduction phase; relu/lrelu merged; tanh&sigmoid share one tanh.approx;
// gelu exact. Writes h as fp16. Fused mask pass-through (fp32).
// ===========================================================================
__global__ __launch_bounds__(256)
void act_kernel(const __half* __restrict__ Z, const int* __restrict__ tids,
                const float* __restrict__ mask, __half* __restrict__ Hout,
                float* __restrict__ MOut)
{
    const int row  = blockIdx.x;
    const int t    = threadIdx.x;
    const int lane = t & 31, wid = t >> 5;
    const size_t base = (size_t)row * H_SZ;

    uint2 zraw = *reinterpret_cast<const uint2*>(Z + base + t * 4);
    float2 z01 = __half22float2(*(__half2*)&zraw.x);
    float2 z23 = __half22float2(*(__half2*)&zraw.y);
    int4  i4 = *reinterpret_cast<const int4*>(tids + t * 4);
    float zr[4] = {z01.x, z01.y, z23.x, z23.y};
    int   tr[4] = {i4.x, i4.y, i4.z, i4.w};

    float E[4];
    float s3 = 0.f, s4 = 0.f;
#pragma unroll
    for (int q = 0; q < 4; q++) {
        bool p3 = (tr[q] == 3), p4 = (tr[q] == 4);
        float sg = p4 ? -zr[q] : zr[q];
        E[q] = __expf(sg);
        s3 += p3 ? E[q] : 0.f;
        s4 += p4 ? E[q] : 0.f;
    }
#pragma unroll
    for (int off = 16; off; off >>= 1) {
        s3 += __shfl_xor_sync(0xffffffffu, s3, off);
        s4 += __shfl_xor_sync(0xffffffffu, s4, off);
    }
    __shared__ float sC[8], sD[8];
    if (lane == 0) { sC[wid] = s3; sD[wid] = s4; }
    __syncthreads();
    s3 = 0.f; s4 = 0.f;
#pragma unroll
    for (int j = 0; j < 8; j++) { s3 += sC[j]; s4 += sD[j]; }
    float r3 = __frcp_rn(s3), r4 = __frcp_rn(s4);

    float4 mk = *reinterpret_cast<const float4*>(mask + base + t * 4);
    float mv[4] = {mk.x, mk.y, mk.z, mk.w};
    float ov[4];
#pragma unroll
    for (int q = 0; q < 4; q++) {
        float x = zr[q];
        int  ty = tr[q];
        float cmin  = (ty == 6) ? LRELU_SLOPE : 0.f;
        float vrelu = fmaxf(x, 0.f) + cmin * fminf(x, 0.f);
        float targ  = (ty == 2) ? 0.5f * x : x;
        float th    = tanh_fast(targ);
        float vtanh = (ty == 2) ? fmaf(0.5f, th, 0.5f) : th;
        float vsoft = E[q] * ((ty == 3) ? r3 : r4);
        float v = (ty <= 0) ? vrelu
                : (ty <= 2) ? vtanh
                : (ty <= 4) ? vsoft
                : vrelu;
        if (ty == 5) v = x * normcdff(x);
        ov[q] = v * mv[q] * KEEP_SCALE;
    }
    __half2 h01 = __floats2half2_rn(ov[0], ov[1]);
    __half2 h23 = __floats2half2_rn(ov[2], ov[3]);
    *reinterpret_cast<uint2*>(Hout + base + t * 4) =
        make_uint2(*(uint32_t*)&h01, *(uint32_t*)&h23);
    *reinterpret_cast<float4*>(MOut + base + t * 4) = mk;
}

// ===========================================================================
// Layer 3 + log_softmax (R8-validated structure, fp16 Hm).
// ===========================================================================
__global__ __launch_bounds__(256)
void layer3_kernel(const __half* __restrict__ Hm, const float* __restrict__ W3,
                   const float* __restrict__ b3, float* __restrict__ Out)
{
    __shared__ float Ws[C_SZ * H_SZ];
    __shared__ float bs[16];
    for (int i = threadIdx.x; i < C_SZ * H_SZ; i += 256) Ws[i] = W3[i];
    if (threadIdx.x < C_SZ) bs[threadIdx.x] = b3[threadIdx.x];
    __syncthreads();

    const int warp = threadIdx.x >> 5;
    const int lane = threadIdx.x & 31;
    const int row0 = blockIdx.x * 64 + warp * 8;   // 8 rows per warp
    const float4* Ws4 = reinterpret_cast<const float4*>(Ws);

    float acc[8][C_SZ];
#pragma unroll
    for (int r = 0; r < 8; r++)
#pragma unroll
        for (int c = 0; c < C_SZ; c++) acc[r][c] = 0.f;

#pragma unroll
    for (int j = 0; j < 8; j++) {
        int idx = lane + 32 * j;
        float4 wv[C_SZ];
#pragma unroll
        for (int c = 0; c < C_SZ; c++) wv[c] = Ws4[c * 256 + idx];
#pragma unroll
        for (int r = 0; r < 8; r++) {
            uint2 hraw = *reinterpret_cast<const uint2*>(
                &Hm[(size_t)(row0 + r) * H_SZ + idx * 4]);
            float2 h01 = __half22float2(*(__half2*)&hraw.x);
            float2 h23 = __half22float2(*(__half2*)&hraw.y);
#pragma unroll
            for (int c = 0; c < C_SZ; c++)
                acc[r][c] += h01.x * wv[c].x + h01.y * wv[c].y
                           + h23.x * wv[c].z + h23.y * wv[c].w;
        }
    }

#pragma unroll
    for (int r = 0; r < 8; r++) {
#pragma unroll
        for (int c = 0; c < C_SZ; c++)
#pragma unroll
            for (int off = 16; off; off >>= 1)
                acc[r][c] += __shfl_xor_sync(0xffffffff, acc[r][c], off);

        if (lane == 0) {
            float l[C_SZ], mx = -INFINITY;
#pragma unroll
            for (int c = 0; c < C_SZ; c++) {
                l[c] = acc[r][c] + bs[c];
                mx = fmaxf(mx, l[c]);
            }
            float s = 0.f;
#pragma unroll
            for (int c = 0; c < C_SZ; c++) s += __expf(l[c] - mx);
            float lse = mx + __logf(s);
#pragma unroll
            for (int c = 0; c < C_SZ; c++)
                Out[(size_t)(row0 + r) * C_SZ + c] = l[c] - lse;
        }
    }
}

// ===========================================================================
extern "C" void kernel_launch(void* const* d_in, const int* in_sizes, int n_in,
                              void* d_out, int out_size)
{
    (void)in_sizes; (void)n_in; (void)out_size;
    const float* x    = (const float*)d_in[0];
    const float* W0   = (const float*)d_in[1];
    const float* b0   = (const float*)d_in[2];
    const float* W1   = (const float*)d_in[3];
    const float* b1   = (const float*)d_in[4];
    const float* W2   = (const float*)d_in[5];
    const float* b2   = (const float*)d_in[6];
    const float* W3   = (const float*)d_in[7];
    const float* b3   = (const float*)d_in[8];
    const float* m1   = (const float*)d_in[9];
    const float* m2   = (const float*)d_in[10];
    const float* m3   = (const float*)d_in[11];
    const int*   tids = (const int*)d_in[12];
    float* out = (float*)d_out;

    __half *z, *h, *xh, *w0h, *w1h, *w2h;
    cudaGetSymbolAddress((void**)&z,  g_z);
    cudaGetSymbolAddress((void**)&h,  g_h);
    cudaGetSymbolAddress((void**)&xh, g_xh);
    cudaGetSymbolAddress((void**)&w0h, g_w0);
    cudaGetSymbolAddress((void**)&w1h, g_w1);
    cudaGetSymbolAddress((void**)&w2h, g_w2);

    cudaFuncSetAttribute(gemm_f16_nt<D_IN>,
                         cudaFuncAttributeMaxDynamicSharedMemorySize, GEMM_SMEM);
    cudaFuncSetAttribute(gemm_f16_nt<H_SZ>,
                         cudaFuncAttributeMaxDynamicSharedMemorySize, GEMM_SMEM);

    cvt_all<<<NB_TOTAL, 256>>>(x, xh, W0, w0h, W1, w1h, W2, w2h);

    dim3 grid(H_SZ / BN, B_SZ / BM);   // (4, 256)
    float* mout = out + (size_t)B_SZ * C_SZ;
    size_t BH = (size_t)B_SZ * H_SZ;

    gemm_f16_nt<D_IN><<<grid, 256, GEMM_SMEM>>>(xh, w0h, b0, z);
    act_kernel<<<B_SZ, 256>>>(z, tids, m1, h, mout);

    gemm_f16_nt<H_SZ><<<grid, 256, GEMM_SMEM>>>(h, w1h, b1, z);
    act_kernel<<<B_SZ, 256>>>(z, tids + H_SZ, m2, h, mout + BH);

    gemm_f16_nt<H_SZ><<<grid, 256, GEMM_SMEM>>>(h, w2h, b2, z);
    act_kernel<<<B_SZ, 256>>>(z, tids + 2 * H_SZ, m3, h, mout + 2 * BH);

    layer3_kernel<<<B_SZ / 64, 256>>>(h, W3, b3, out);
}

// round 16
// speedup vs baseline: 2.8008x; 1.0329x over previous
#include <cuda_runtime.h>
#include <cuda_fp16.h>
#include <math.h>
#include <stdint.h>

#define B_SZ 32768
#define H_SZ 1024
#define D_IN 784
#define C_SZ 10
#define KEEP_SCALE 2.0f
#define LRELU_SLOPE 0.01f

// Scratch (device globals — allocation is forbidden)
__device__ __half g_z[(size_t)B_SZ * H_SZ];        // pre-activation (fp16)
__device__ __half g_h[(size_t)B_SZ * H_SZ];        // activations (fp16)
__device__ __half g_xh[(size_t)B_SZ * D_IN];       // x converted to fp16
__device__ __half g_w0[(size_t)H_SZ * D_IN];       // W0 fp16
__device__ __half g_w1[(size_t)H_SZ * H_SZ];       // W1 fp16
__device__ __half g_w2[(size_t)H_SZ * H_SZ];       // W2 fp16

// ===========================================================================
// Helpers
// ===========================================================================
__device__ __forceinline__ uint32_t smem_u32(const void* p) {
    uint32_t a;
    asm("{ .reg .u64 t; cvta.to.shared.u64 t, %1; cvt.u32.u64 %0, t; }"
        : "=r"(a) : "l"(p));
    return a;
}

__device__ __forceinline__ void cp_async16(uint32_t dst, const void* src, int src_bytes) {
    asm volatile("cp.async.cg.shared.global [%0], [%1], 16, %2;"
                 :: "r"(dst), "l"(src), "r"(src_bytes) : "memory");
}

__device__ __forceinline__ float tanh_fast(float x) {
    float r;
    asm("tanh.approx.f32 %0, %1;" : "=f"(r) : "f"(x));
    return r;
}

#define LDSM_X4(r0, r1, r2, r3, addr) \
    asm volatile("ldmatrix.sync.aligned.m8n8.x4.shared.b16 {%0,%1,%2,%3}, [%4];" \
                 : "=r"(r0), "=r"(r1), "=r"(r2), "=r"(r3) : "r"(addr))

__device__ __forceinline__ void mma_f16(float* d, const uint32_t* a, const uint32_t* b) {
    asm volatile(
        "mma.sync.aligned.m16n8k16.row.col.f32.f16.f16.f32 "
        "{%0,%1,%2,%3}, {%4,%5,%6,%7}, {%8,%9}, {%0,%1,%2,%3};"
        : "+f"(d[0]), "+f"(d[1]), "+f"(d[2]), "+f"(d[3])
        : "r"(a[0]), "r"(a[1]), "r"(a[2]), "r"(a[3]), "r"(b[0]), "r"(b[1]));
}

// ===========================================================================
// Fused fp32 -> fp16 conversion for x, W0, W1, W2 in ONE launch.
// ===========================================================================
#define NB_X  ((B_SZ * D_IN) / 1024)             // 25088
#define NB_W0 ((H_SZ * D_IN) / 1024)             // 784
#define NB_W  ((H_SZ * H_SZ) / 1024)             // 1024
#define NB_TOTAL (NB_X + NB_W0 + 2 * NB_W)       // 27920

__global__ __launch_bounds__(256)
void cvt_all(const float* __restrict__ x,  __half* __restrict__ xh,
             const float* __restrict__ w0, __half* __restrict__ w0h,
             const float* __restrict__ w1, __half* __restrict__ w1h,
             const float* __restrict__ w2, __half* __restrict__ w2h)
{
    int b = blockIdx.x;
    const float* src; __half* dst; size_t off;
    if (b < NB_X)                       { src = x;  dst = xh;  off = (size_t)b; }
    else if (b < NB_X + NB_W0)          { src = w0; dst = w0h; off = (size_t)(b - NB_X); }
    else if (b < NB_X + NB_W0 + NB_W)   { src = w1; dst = w1h; off = (size_t)(b - NB_X - NB_W0); }
    else                                { src = w2; dst = w2h; off = (size_t)(b - NB_X - NB_W0 - NB_W); }
    size_t i = (off * 1024) + (size_t)threadIdx.x * 4;
    float4 v = *reinterpret_cast<const float4*>(src + i);
    __half2 h01 = __floats2half2_rn(v.x, v.y);
    __half2 h23 = __floats2half2_rn(v.z, v.w);
    *reinterpret_cast<uint2*>(dst + i) =
        make_uint2(*(uint32_t*)&h01, *(uint32_t*)&h23);
}

// ===========================================================================
// fp16 mma.sync GEMM: Z[m,n] = sum_k A[m,k]*W[n,k] + bias[n]  (fp16 out)
// CTA 128x128, BK=64 halves, 128 threads (4 warps 2x2, warp tile 64x64).
// 3-stage pipeline, 108KB smem -> 2 CTAs/SM to fill tensor-pipe bubbles.
// Fragments via ldmatrix.x4.
// ===========================================================================
#define BM 128
#define BN 128
#define BK 64                                   // halves
#define PADH 72                                 // halves per row (36 words)
#define NSTAGE 3
#define STG_HALVES ((BM + BN) * PADH)           // 18432 halves = 36864 B
#define GEMM_SMEM (NSTAGE * STG_HALVES * 2)     // 110592 bytes

template <int K>
__global__ __launch_bounds__(128, 2)
void gemm_f16_nt(const __half* __restrict__ A, const __half* __restrict__ W,
                 const float* __restrict__ bias, __half* __restrict__ Z)
{
    constexpr int NK = (K + BK - 1) / BK;

    extern __shared__ __align__(16) __half sm[];

    const int tid  = threadIdx.x;
    const int wid  = tid >> 5;
    const int lane = tid & 31;
    const int warpM = (wid & 1) * 64;       // 2 warp-rows
    const int warpN = (wid >> 1) * 64;      // 2 warp-cols
    const int bm = blockIdx.y * BM;
    const int bn = blockIdx.x * BN;

    const __half* Ag = A + (size_t)bm * K;
    const __half* Wg = W + (size_t)bn * K;

    const uint32_t sm_u = smem_u32(sm);
    const uint32_t aoff = 2u * ((warpM + (lane & 15)) * PADH + ((lane >> 4) << 3));
    const uint32_t boff = 2u * (BM * PADH
                        + (warpN + ((lane >> 4) << 3) + (lane & 7)) * PADH
                        + (((lane >> 3) & 1) << 3));

    float acc[4][8][4];
#pragma unroll
    for (int i = 0; i < 4; i++)
#pragma unroll
        for (int j = 0; j < 8; j++)
#pragma unroll
            for (int q = 0; q < 4; q++) acc[i][j][q] = 0.f;

    auto load_stage = [&](int s, int kc) {
        const int k0 = kc * BK;
        __half* As = sm + s * STG_HALVES;
        __half* Bs = As + BM * PADH;
        // A: 128 rows x 8 granules(16B) = 1024 granules over 128 threads
#pragma unroll
        for (int it = 0; it < 8; it++) {
            int idx = tid + it * 128;
            int row = idx >> 3, q = idx & 7;
            int gk  = k0 + q * 8;
            int sb  = (K % BK == 0) ? 16 : ((gk < K) ? 16 : 0);
            int gkc = (K % BK == 0) ? gk : min(gk, K - 8);
            cp_async16(smem_u32(&As[row * PADH + q * 8]),
                       Ag + (size_t)row * K + gkc, sb);
        }
        // B: 128 rows x 8 granules = 1024 granules
#pragma unroll
        for (int it = 0; it < 8; it++) {
            int idx = tid + it * 128;
            int row = idx >> 3, q = idx & 7;
            int gk  = k0 + q * 8;
            int sb  = (K % BK == 0) ? 16 : ((gk < K) ? 16 : 0);
            int gkc = (K % BK == 0) ? gk : min(gk, K - 8);
            cp_async16(smem_u32(&Bs[row * PADH + q * 8]),
                       Wg + (size_t)row * K + gkc, sb);
        }
    };

    // Prologue: stages 0..NSTAGE-2
#pragma unroll
    for (int s = 0; s < NSTAGE - 1; s++) {
        load_stage(s, s);
        asm volatile("cp.async.commit_group;" ::: "memory");
    }

    int buf = 0, nxt = NSTAGE - 1;
#pragma unroll 1
    for (int ki = 0; ki < NK; ki++) {
        asm volatile("cp.async.wait_group 1;" ::: "memory");
        __syncthreads();

        const uint32_t stg = sm_u + (uint32_t)(buf * STG_HALVES * 2);
        const uint32_t aBase = stg + aoff;
        const uint32_t bBase = stg + boff;

#pragma unroll
        for (int ks = 0; ks < 4; ks++) {
            const uint32_t kd = ks * 32;

            uint32_t af[4][4];
#pragma unroll
            for (int i = 0; i < 4; i++)
                LDSM_X4(af[i][0], af[i][1], af[i][2], af[i][3],
                        aBase + i * (16 * PADH * 2) + kd);
            uint32_t bf[8][2];
#pragma unroll
            for (int jp = 0; jp < 4; jp++)
                LDSM_X4(bf[2 * jp][0], bf[2 * jp][1],
                        bf[2 * jp + 1][0], bf[2 * jp + 1][1],
                        bBase + jp * (16 * PADH * 2) + kd);
#pragma unroll
            for (int i = 0; i < 4; i++)
#pragma unroll
                for (int j = 0; j < 8; j++)
                    mma_f16(acc[i][j], af[i], bf[j]);
        }

        const int kn = ki + NSTAGE - 1;
        if (kn < NK) load_stage(nxt, kn);
        asm volatile("cp.async.commit_group;" ::: "memory");
        buf = (buf + 1 == NSTAGE) ? 0 : buf + 1;
        nxt = (nxt + 1 == NSTAGE) ? 0 : nxt + 1;
    }

    // Epilogue: bias + store (fp16)
    const int g   = lane >> 2;
    const int tig = lane & 3;
#pragma unroll
    for (int i = 0; i < 4; i++) {
        int row0 = bm + warpM + 16 * i + g;
#pragma unroll
        for (int j = 0; j < 8; j++) {
            int col = bn + warpN + 8 * j + 2 * tig;
            float2 bi = *reinterpret_cast<const float2*>(&bias[col]);
            __half2 v0 = __floats2half2_rn(acc[i][j][0] + bi.x, acc[i][j][1] + bi.y);
            __half2 v1 = __floats2half2_rn(acc[i][j][2] + bi.x, acc[i][j][3] + bi.y);
            *reinterpret_cast<__half2*>(&Z[(size_t)row0 * H_SZ + col]) = v0;
            *reinterpret_cast<__half2*>(&Z[(size_t)(row0 + 8) * H_SZ + col]) = v1;
        }
    }
}

// ===========================================================================
// Mixed activation (R8-validated structure, fp16 z input).
// ===========================================================================
__global__ __launch_bounds__(256)
void act_kernel(const __half* __restrict__ Z, const int* __restrict__ tids,
                const float* __restrict__ mask, __half* __restrict__ Hout,
                float* __restrict__ MOut)
{
    const int row  = blockIdx.x;
    const int t    = threadIdx.x;
    const int lane = t & 31, wid = t >> 5;
    const size_t base = (size_t)row * H_SZ;

    uint2 zraw = *reinterpret_cast<const uint2*>(Z + base + t * 4);
    float2 z01 = __half22float2(*(__half2*)&zraw.x);
    float2 z23 = __half22float2(*(__half2*)&zraw.y);
    int4  i4 = *reinterpret_cast<const int4*>(tids + t * 4);
    float zr[4] = {z01.x, z01.y, z23.x, z23.y};
    int   tr[4] = {i4.x, i4.y, i4.z, i4.w};

    float E[4];
    float s3 = 0.f, s4 = 0.f;
#pragma unroll
    for (int q = 0; q < 4; q++) {
        bool p3 = (tr[q] == 3), p4 = (tr[q] == 4);
        float sg = p4 ? -zr[q] : zr[q];
        E[q] = __expf(sg);
        s3 += p3 ? E[q] : 0.f;
        s4 += p4 ? E[q] : 0.f;
    }
#pragma unroll
    for (int off = 16; off; off >>= 1) {
        s3 += __shfl_xor_sync(0xffffffffu, s3, off);
        s4 += __shfl_xor_sync(0xffffffffu, s4, off);
    }
    __shared__ float sC[8], sD[8];
    if (lane == 0) { sC[wid] = s3; sD[wid] = s4; }
    __syncthreads();
    s3 = 0.f; s4 = 0.f;
#pragma unroll
    for (int j = 0; j < 8; j++) { s3 += sC[j]; s4 += sD[j]; }
    float r3 = __frcp_rn(s3), r4 = __frcp_rn(s4);

    float4 mk = *reinterpret_cast<const float4*>(mask + base + t * 4);
    float mv[4] = {mk.x, mk.y, mk.z, mk.w};
    float ov[4];
#pragma unroll
    for (int q = 0; q < 4; q++) {
        float x = zr[q];
        int  ty = tr[q];
        float cmin  = (ty == 6) ? LRELU_SLOPE : 0.f;
        float vrelu = fmaxf(x, 0.f) + cmin * fminf(x, 0.f);
        float targ  = (ty == 2) ? 0.5f * x : x;
        float th    = tanh_fast(targ);
        float vtanh = (ty == 2) ? fmaf(0.5f, th, 0.5f) : th;
        float vsoft = E[q] * ((ty == 3) ? r3 : r4);
        float v = (ty <= 0) ? vrelu
                : (ty <= 2) ? vtanh
                : (ty <= 4) ? vsoft
                : vrelu;
        if (ty == 5) v = x * normcdff(x);
        ov[q] = v * mv[q] * KEEP_SCALE;
    }
    __half2 h01 = __floats2half2_rn(ov[0], ov[1]);
    __half2 h23 = __floats2half2_rn(ov[2], ov[3]);
    *reinterpret_cast<uint2*>(Hout + base + t * 4) =
        make_uint2(*(uint32_t*)&h01, *(uint32_t*)&h23);
    *reinterpret_cast<float4*>(MOut + base + t * 4) = mk;
}

// ===========================================================================
// Layer 3 + log_softmax (R8-validated structure, fp16 Hm).
// ===========================================================================
__global__ __launch_bounds__(256)
void layer3_kernel(const __half* __restrict__ Hm, const float* __restrict__ W3,
                   const float* __restrict__ b3, float* __restrict__ Out)
{
    __shared__ float Ws[C_SZ * H_SZ];
    __shared__ float bs[16];
    for (int i = threadIdx.x; i < C_SZ * H_SZ; i += 256) Ws[i] = W3[i];
    if (threadIdx.x < C_SZ) bs[threadIdx.x] = b3[threadIdx.x];
    __syncthreads();

    const int warp = threadIdx.x >> 5;
    const int lane = threadIdx.x & 31;
    const int row0 = blockIdx.x * 64 + warp * 8;   // 8 rows per warp
    const float4* Ws4 = reinterpret_cast<const float4*>(Ws);

    float acc[8][C_SZ];
#pragma unroll
    for (int r = 0; r < 8; r++)
#pragma unroll
        for (int c = 0; c < C_SZ; c++) acc[r][c] = 0.f;

#pragma unroll
    for (int j = 0; j < 8; j++) {
        int idx = lane + 32 * j;
        float4 wv[C_SZ];
#pragma unroll
        for (int c = 0; c < C_SZ; c++) wv[c] = Ws4[c * 256 + idx];
#pragma unroll
        for (int r = 0; r < 8; r++) {
            uint2 hraw = *reinterpret_cast<const uint2*>(
                &Hm[(size_t)(row0 + r) * H_SZ + idx * 4]);
            float2 h01 = __half22float2(*(__half2*)&hraw.x);
            float2 h23 = __half22float2(*(__half2*)&hraw.y);
#pragma unroll
            for (int c = 0; c < C_SZ; c++)
                acc[r][c] += h01.x * wv[c].x + h01.y * wv[c].y
                           + h23.x * wv[c].z + h23.y * wv[c].w;
        }
    }

#pragma unroll
    for (int r = 0; r < 8; r++) {
#pragma unroll
        for (int c = 0; c < C_SZ; c++)
#pragma unroll
            for (int off = 16; off; off >>= 1)
                acc[r][c] += __shfl_xor_sync(0xffffffff, acc[r][c], off);

        if (lane == 0) {
            float l[C_SZ], mx = -INFINITY;
#pragma unroll
            for (int c = 0; c < C_SZ; c++) {
                l[c] = acc[r][c] + bs[c];
                mx = fmaxf(mx, l[c]);
            }
            float s = 0.f;
#pragma unroll
            for (int c = 0; c < C_SZ; c++) s += __expf(l[c] - mx);
            float lse = mx + __logf(s);
#pragma unroll
            for (int c = 0; c < C_SZ; c++)
                Out[(size_t)(row0 + r) * C_SZ + c] = l[c] - lse;
        }
    }
}

// ===========================================================================
extern "C" void kernel_launch(void* const* d_in, const int* in_sizes, int n_in,
                              void* d_out, int out_size)
{
    (void)in_sizes; (void)n_in; (void)out_size;
    const float* x    = (const float*)d_in[0];
    const float* W0   = (const float*)d_in[1];
    const float* b0   = (const float*)d_in[2];
    const float* W1   = (const float*)d_in[3];
    const float* b1   = (const float*)d_in[4];
    const float* W2   = (const float*)d_in[5];
    const float* b2   = (const float*)d_in[6];
    const float* W3   = (const float*)d_in[7];
    const float* b3   = (const float*)d_in[8];
    const float* m1   = (const float*)d_in[9];
    const float* m2   = (const float*)d_in[10];
    const float* m3   = (const float*)d_in[11];
    const int*   tids = (const int*)d_in[12];
    float* out = (float*)d_out;

    __half *z, *h, *xh, *w0h, *w1h, *w2h;
    cudaGetSymbolAddress((void**)&z,  g_z);
    cudaGetSymbolAddress((void**)&h,  g_h);
    cudaGetSymbolAddress((void**)&xh, g_xh);
    cudaGetSymbolAddress((void**)&w0h, g_w0);
    cudaGetSymbolAddress((void**)&w1h, g_w1);
    cudaGetSymbolAddress((void**)&w2h, g_w2);

    cudaFuncSetAttribute(gemm_f16_nt<D_IN>,
                         cudaFuncAttributeMaxDynamicSharedMemorySize, GEMM_SMEM);
    cudaFuncSetAttribute(gemm_f16_nt<H_SZ>,
                         cudaFuncAttributeMaxDynamicSharedMemorySize, GEMM_SMEM);

    cvt_all<<<NB_TOTAL, 256>>>(x, xh, W0, w0h, W1, w1h, W2, w2h);

    dim3 grid(H_SZ / BN, B_SZ / BM);   // (8, 256)
    float* mout = out + (size_t)B_SZ * C_SZ;
    size_t BH = (size_t)B_SZ * H_SZ;

    gemm_f16_nt<D_IN><<<grid, 128, GEMM_SMEM>>>(xh, w0h, b0, z);
    act_kernel<<<B_SZ, 256>>>(z, tids, m1, h, mout);

    gemm_f16_nt<H_SZ><<<grid, 128, GEMM_SMEM>>>(h, w1h, b1, z);
    act_kernel<<<B_SZ, 256>>>(z, tids + H_SZ, m2, h, mout + BH);

    gemm_f16_nt<H_SZ><<<grid, 128, GEMM_SMEM>>>(h, w2h, b2, z);
    act_kernel<<<B_SZ, 256>>>(z, tids + 2 * H_SZ, m3, h, mout + 2 * BH);

    layer3_kernel<<<B_SZ / 64, 256>>>(h, W3, b3, out);
}

// round 17
// speedup vs baseline: 2.8367x; 1.0128x over previous
#include <cuda_runtime.h>
#include <cuda_fp16.h>
#include <math.h>
#include <stdint.h>

#define B_SZ 32768
#define H_SZ 1024
#define D_IN 784
#define C_SZ 10
#define KEEP_SCALE 2.0f
#define LRELU_SLOPE 0.01f

// Scratch (device globals — allocation is forbidden)
__device__ __half g_z[(size_t)B_SZ * H_SZ];        // pre-activation (fp16)
__device__ __half g_h[(size_t)B_SZ * H_SZ];        // activations (fp16)
__device__ __half g_xh[(size_t)B_SZ * D_IN];       // x converted to fp16
__device__ __half g_w0[(size_t)H_SZ * D_IN];       // W0 fp16
__device__ __half g_w1[(size_t)H_SZ * H_SZ];       // W1 fp16
__device__ __half g_w2[(size_t)H_SZ * H_SZ];       // W2 fp16

// ===========================================================================
// Helpers
// ===========================================================================
__device__ __forceinline__ uint32_t smem_u32(const void* p) {
    uint32_t a;
    asm("{ .reg .u64 t; cvta.to.shared.u64 t, %1; cvt.u32.u64 %0, t; }"
        : "=r"(a) : "l"(p));
    return a;
}

__device__ __forceinline__ void cp_async16(uint32_t dst, const void* src, int src_bytes) {
    asm volatile("cp.async.cg.shared.global [%0], [%1], 16, %2;"
                 :: "r"(dst), "l"(src), "r"(src_bytes) : "memory");
}

__device__ __forceinline__ float tanh_fast(float x) {
    float r;
    asm("tanh.approx.f32 %0, %1;" : "=f"(r) : "f"(x));
    return r;
}

#define LDSM_X4(r0, r1, r2, r3, addr) \
    asm volatile("ldmatrix.sync.aligned.m8n8.x4.shared.b16 {%0,%1,%2,%3}, [%4];" \
                 : "=r"(r0), "=r"(r1), "=r"(r2), "=r"(r3) : "r"(addr))

__device__ __forceinline__ void mma_f16(float* d, const uint32_t* a, const uint32_t* b) {
    asm volatile(
        "mma.sync.aligned.m16n8k16.row.col.f32.f16.f16.f32 "
        "{%0,%1,%2,%3}, {%4,%5,%6,%7}, {%8,%9}, {%0,%1,%2,%3};"
        : "+f"(d[0]), "+f"(d[1]), "+f"(d[2]), "+f"(d[3])
        : "r"(a[0]), "r"(a[1]), "r"(a[2]), "r"(a[3]), "r"(b[0]), "r"(b[1]));
}

// ===========================================================================
// Fused fp32 -> fp16 conversion for x, W0, W1, W2 in ONE launch.
// ===========================================================================
#define NB_X  ((B_SZ * D_IN) / 1024)             // 25088
#define NB_W0 ((H_SZ * D_IN) / 1024)             // 784
#define NB_W  ((H_SZ * H_SZ) / 1024)             // 1024
#define NB_TOTAL (NB_X + NB_W0 + 2 * NB_W)       // 27920

__global__ __launch_bounds__(256)
void cvt_all(const float* __restrict__ x,  __half* __restrict__ xh,
             const float* __restrict__ w0, __half* __restrict__ w0h,
             const float* __restrict__ w1, __half* __restrict__ w1h,
             const float* __restrict__ w2, __half* __restrict__ w2h)
{
    int b = blockIdx.x;
    const float* src; __half* dst; size_t off;
    if (b < NB_X)                       { src = x;  dst = xh;  off = (size_t)b; }
    else if (b < NB_X + NB_W0)          { src = w0; dst = w0h; off = (size_t)(b - NB_X); }
    else if (b < NB_X + NB_W0 + NB_W)   { src = w1; dst = w1h; off = (size_t)(b - NB_X - NB_W0); }
    else                                { src = w2; dst = w2h; off = (size_t)(b - NB_X - NB_W0 - NB_W); }
    size_t i = (off * 1024) + (size_t)threadIdx.x * 4;
    float4 v = *reinterpret_cast<const float4*>(src + i);
    __half2 h01 = __floats2half2_rn(v.x, v.y);
    __half2 h23 = __floats2half2_rn(v.z, v.w);
    *reinterpret_cast<uint2*>(dst + i) =
        make_uint2(*(uint32_t*)&h01, *(uint32_t*)&h23);
}

// ===========================================================================
// fp16 mma.sync GEMM: Z[m,n] = sum_k A[m,k]*W[n,k] + bias[n]  (fp16 out)
// CTA 128x128, BK=64 halves, 128 threads (4 warps 2x2, warp tile 64x64).
// 2-stage pipeline, 73.7KB smem -> 3 CTAs/SM (cross-CTA bubble hiding).
// Loads for stage k+1 issued BEFORE the MMA block (overlap with compute).
// ===========================================================================
#define BM 128
#define BN 128
#define BK 64                                   // halves
#define PADH 72                                 // halves per row (36 words)
#define NSTAGE 2
#define STG_HALVES ((BM + BN) * PADH)           // 18432 halves = 36864 B
#define GEMM_SMEM (NSTAGE * STG_HALVES * 2)     // 73728 bytes

template <int K>
__global__ __launch_bounds__(128, 3)
void gemm_f16_nt(const __half* __restrict__ A, const __half* __restrict__ W,
                 const float* __restrict__ bias, __half* __restrict__ Z)
{
    constexpr int NK = (K + BK - 1) / BK;

    extern __shared__ __align__(16) __half sm[];

    const int tid  = threadIdx.x;
    const int wid  = tid >> 5;
    const int lane = tid & 31;
    const int warpM = (wid & 1) * 64;       // 2 warp-rows
    const int warpN = (wid >> 1) * 64;      // 2 warp-cols
    const int bm = blockIdx.y * BM;
    const int bn = blockIdx.x * BN;

    const __half* Ag = A + (size_t)bm * K;
    const __half* Wg = W + (size_t)bn * K;

    const uint32_t sm_u = smem_u32(sm);
    const uint32_t aoff = 2u * ((warpM + (lane & 15)) * PADH + ((lane >> 4) << 3));
    const uint32_t boff = 2u * (BM * PADH
                        + (warpN + ((lane >> 4) << 3) + (lane & 7)) * PADH
                        + (((lane >> 3) & 1) << 3));

    float acc[4][8][4];
#pragma unroll
    for (int i = 0; i < 4; i++)
#pragma unroll
        for (int j = 0; j < 8; j++)
#pragma unroll
            for (int q = 0; q < 4; q++) acc[i][j][q] = 0.f;

    auto load_stage = [&](int s, int kc) {
        const int k0 = kc * BK;
        __half* As = sm + s * STG_HALVES;
        __half* Bs = As + BM * PADH;
#pragma unroll
        for (int it = 0; it < 8; it++) {
            int idx = tid + it * 128;
            int row = idx >> 3, q = idx & 7;
            int gk  = k0 + q * 8;
            int sb  = (K % BK == 0) ? 16 : ((gk < K) ? 16 : 0);
            int gkc = (K % BK == 0) ? gk : min(gk, K - 8);
            cp_async16(smem_u32(&As[row * PADH + q * 8]),
                       Ag + (size_t)row * K + gkc, sb);
        }
#pragma unroll
        for (int it = 0; it < 8; it++) {
            int idx = tid + it * 128;
            int row = idx >> 3, q = idx & 7;
            int gk  = k0 + q * 8;
            int sb  = (K % BK == 0) ? 16 : ((gk < K) ? 16 : 0);
            int gkc = (K % BK == 0) ? gk : min(gk, K - 8);
            cp_async16(smem_u32(&Bs[row * PADH + q * 8]),
                       Wg + (size_t)row * K + gkc, sb);
        }
    };

    // Prologue: stage 0
    load_stage(0, 0);
    asm volatile("cp.async.commit_group;" ::: "memory");

#pragma unroll 1
    for (int ki = 0; ki < NK; ki++) {
        const int buf = ki & 1;
        asm volatile("cp.async.wait_group 0;" ::: "memory");
        __syncthreads();

        // Issue next-stage loads FIRST so they overlap the MMA block below.
        // Safe: the syncthreads above guarantees nobody still reads buf^1.
        if (ki + 1 < NK) load_stage(buf ^ 1, ki + 1);
        asm volatile("cp.async.commit_group;" ::: "memory");

        const uint32_t stg = sm_u + (uint32_t)(buf * STG_HALVES * 2);
        const uint32_t aBase = stg + aoff;
        const uint32_t bBase = stg + boff;

#pragma unroll
        for (int ks = 0; ks < 4; ks++) {
            const uint32_t kd = ks * 32;

            uint32_t af[4][4];
#pragma unroll
            for (int i = 0; i < 4; i++)
                LDSM_X4(af[i][0], af[i][1], af[i][2], af[i][3],
                        aBase + i * (16 * PADH * 2) + kd);
            uint32_t bf[8][2];
#pragma unroll
            for (int jp = 0; jp < 4; jp++)
                LDSM_X4(bf[2 * jp][0], bf[2 * jp][1],
                        bf[2 * jp + 1][0], bf[2 * jp + 1][1],
                        bBase + jp * (16 * PADH * 2) + kd);
#pragma unroll
            for (int i = 0; i < 4; i++)
#pragma unroll
                for (int j = 0; j < 8; j++)
                    mma_f16(acc[i][j], af[i], bf[j]);
        }
    }

    // Epilogue: bias + store (fp16)
    const int g   = lane >> 2;
    const int tig = lane & 3;
#pragma unroll
    for (int i = 0; i < 4; i++) {
        int row0 = bm + warpM + 16 * i + g;
#pragma unroll
        for (int j = 0; j < 8; j++) {
            int col = bn + warpN + 8 * j + 2 * tig;
            float2 bi = *reinterpret_cast<const float2*>(&bias[col]);
            __half2 v0 = __floats2half2_rn(acc[i][j][0] + bi.x, acc[i][j][1] + bi.y);
            __half2 v1 = __floats2half2_rn(acc[i][j][2] + bi.x, acc[i][j][3] + bi.y);
            *reinterpret_cast<__half2*>(&Z[(size_t)row0 * H_SZ + col]) = v0;
            *reinterpret_cast<__half2*>(&Z[(size_t)(row0 + 8) * H_SZ + col]) = v1;
        }
    }
}

// ===========================================================================
// Mixed activation (R8-validated structure, fp16 z input).
// ===========================================================================
__global__ __launch_bounds__(256)
void act_kernel(const __half* __restrict__ Z, const int* __restrict__ tids,
                const float* __restrict__ mask, __half* __restrict__ Hout,
                float* __restrict__ MOut)
{
    const int row  = blockIdx.x;
    const int t    = threadIdx.x;
    const int lane = t & 31, wid = t >> 5;
    const size_t base = (size_t)row * H_SZ;

    uint2 zraw = *reinterpret_cast<const uint2*>(Z + base + t * 4);
    float2 z01 = __half22float2(*(__half2*)&zraw.x);
    float2 z23 = __half22float2(*(__half2*)&zraw.y);
    int4  i4 = *reinterpret_cast<const int4*>(tids + t * 4);
    float zr[4] = {z01.x, z01.y, z23.x, z23.y};
    int   tr[4] = {i4.x, i4.y, i4.z, i4.w};

    float E[4];
    float s3 = 0.f, s4 = 0.f;
#pragma unroll
    for (int q = 0; q < 4; q++) {
        bool p3 = (tr[q] == 3), p4 = (tr[q] == 4);
        float sg = p4 ? -zr[q] : zr[q];
        E[q] = __expf(sg);
        s3 += p3 ? E[q] : 0.f;
        s4 += p4 ? E[q] : 0.f;
    }
#pragma unroll
    for (int off = 16; off; off >>= 1) {
        s3 += __shfl_xor_sync(0xffffffffu, s3, off);
        s4 += __shfl_xor_sync(0xffffffffu, s4, off);
    }
    __shared__ float sC[8], sD[8];
    if (lane == 0) { sC[wid] = s3; sD[wid] = s4; }
    __syncthreads();
    s3 = 0.f; s4 = 0.f;
#pragma unroll
    for (int j = 0; j < 8; j++) { s3 += sC[j]; s4 += sD[j]; }
    float r3 = __frcp_rn(s3), r4 = __frcp_rn(s4);

    float4 mk = *reinterpret_cast<const float4*>(mask + base + t * 4);
    float mv[4] = {mk.x, mk.y, mk.z, mk.w};
    float ov[4];
#pragma unroll
    for (int q = 0; q < 4; q++) {
        float x = zr[q];
        int  ty = tr[q];
        float cmin  = (ty == 6) ? LRELU_SLOPE : 0.f;
        float vrelu = fmaxf(x, 0.f) + cmin * fminf(x, 0.f);
        float targ  = (ty == 2) ? 0.5f * x : x;
        float th    = tanh_fast(targ);
        float vtanh = (ty == 2) ? fmaf(0.5f, th, 0.5f) : th;
        float vsoft = E[q] * ((ty == 3) ? r3 : r4);
        float v = (ty <= 0) ? vrelu
                : (ty <= 2) ? vtanh
                : (ty <= 4) ? vsoft
                : vrelu;
        if (ty == 5) v = x * normcdff(x);
        ov[q] = v * mv[q] * KEEP_SCALE;
    }
    __half2 h01 = __floats2half2_rn(ov[0], ov[1]);
    __half2 h23 = __floats2half2_rn(ov[2], ov[3]);
    *reinterpret_cast<uint2*>(Hout + base + t * 4) =
        make_uint2(*(uint32_t*)&h01, *(uint32_t*)&h23);
    *reinterpret_cast<float4*>(MOut + base + t * 4) = mk;
}

// ===========================================================================
// Layer 3 + log_softmax (R8-validated structure, fp16 Hm).
// ===========================================================================
__global__ __launch_bounds__(256)
void layer3_kernel(const __half* __restrict__ Hm, const float* __restrict__ W3,
                   const float* __restrict__ b3, float* __restrict__ Out)
{
    __shared__ float Ws[C_SZ * H_SZ];
    __shared__ float bs[16];
    for (int i = threadIdx.x; i < C_SZ * H_SZ; i += 256) Ws[i] = W3[i];
    if (threadIdx.x < C_SZ) bs[threadIdx.x] = b3[threadIdx.x];
    __syncthreads();

    const int warp = threadIdx.x >> 5;
    const int lane = threadIdx.x & 31;
    const int row0 = blockIdx.x * 64 + warp * 8;   // 8 rows per warp
    const float4* Ws4 = reinterpret_cast<const float4*>(Ws);

    float acc[8][C_SZ];
#pragma unroll
    for (int r = 0; r < 8; r++)
#pragma unroll
        for (int c = 0; c < C_SZ; c++) acc[r][c] = 0.f;

#pragma unroll
    for (int j = 0; j < 8; j++) {
        int idx = lane + 32 * j;
        float4 wv[C_SZ];
#pragma unroll
        for (int c = 0; c < C_SZ; c++) wv[c] = Ws4[c * 256 + idx];
#pragma unroll
        for (int r = 0; r < 8; r++) {
            uint2 hraw = *reinterpret_cast<const uint2*>(
                &Hm[(size_t)(row0 + r) * H_SZ + idx * 4]);
            float2 h01 = __half22float2(*(__half2*)&hraw.x);
            float2 h23 = __half22float2(*(__half2*)&hraw.y);
#pragma unroll
            for (int c = 0; c < C_SZ; c++)
                acc[r][c] += h01.x * wv[c].x + h01.y * wv[c].y
                           + h23.x * wv[c].z + h23.y * wv[c].w;
        }
    }

#pragma unroll
    for (int r = 0; r < 8; r++) {
#pragma unroll
        for (int c = 0; c < C_SZ; c++)
#pragma unroll
            for (int off = 16; off; off >>= 1)
                acc[r][c] += __shfl_xor_sync(0xffffffff, acc[r][c], off);

        if (lane == 0) {
            float l[C_SZ], mx = -INFINITY;
#pragma unroll
            for (int c = 0; c < C_SZ; c++) {
                l[c] = acc[r][c] + bs[c];
                mx = fmaxf(mx, l[c]);
            }
            float s = 0.f;
#pragma unroll
            for (int c = 0; c < C_SZ; c++) s += __expf(l[c] - mx);
            float lse = mx + __logf(s);
#pragma unroll
            for (int c = 0; c < C_SZ; c++)
                Out[(size_t)(row0 + r) * C_SZ + c] = l[c] - lse;
        }
    }
}

// ===========================================================================
extern "C" void kernel_launch(void* const* d_in, const int* in_sizes, int n_in,
                              void* d_out, int out_size)
{
    (void)in_sizes; (void)n_in; (void)out_size;
    const float* x    = (const float*)d_in[0];
    const float* W0   = (const float*)d_in[1];
    const float* b0   = (const float*)d_in[2];
    const float* W1   = (const float*)d_in[3];
    const float* b1   = (const float*)d_in[4];
    const float* W2   = (const float*)d_in[5];
    const float* b2   = (const float*)d_in[6];
    const float* W3   = (const float*)d_in[7];
    const float* b3   = (const float*)d_in[8];
    const float* m1   = (const float*)d_in[9];
    const float* m2   = (const float*)d_in[10];
    const float* m3   = (const float*)d_in[11];
    const int*   tids = (const int*)d_in[12];
    float* out = (float*)d_out;

    __half *z, *h, *xh, *w0h, *w1h, *w2h;
    cudaGetSymbolAddress((void**)&z,  g_z);
    cudaGetSymbolAddress((void**)&h,  g_h);
    cudaGetSymbolAddress((void**)&xh, g_xh);
    cudaGetSymbolAddress((void**)&w0h, g_w0);
    cudaGetSymbolAddress((void**)&w1h, g_w1);
    cudaGetSymbolAddress((void**)&w2h, g_w2);

    cudaFuncSetAttribute(gemm_f16_nt<D_IN>,
                         cudaFuncAttributeMaxDynamicSharedMemorySize, GEMM_SMEM);
    cudaFuncSetAttribute(gemm_f16_nt<H_SZ>,
                         cudaFuncAttributeMaxDynamicSharedMemorySize, GEMM_SMEM);

    cvt_all<<<NB_TOTAL, 256>>>(x, xh, W0, w0h, W1, w1h, W2, w2h);

    dim3 grid(H_SZ / BN, B_SZ / BM);   // (8, 256)
    float* mout = out + (size_t)B_SZ * C_SZ;
    size_t BH = (size_t)B_SZ * H_SZ;

    gemm_f16_nt<D_IN><<<grid, 128, GEMM_SMEM>>>(xh, w0h, b0, z);
    act_kernel<<<B_SZ, 256>>>(z, tids, m1, h, mout);

    gemm_f16_nt<H_SZ><<<grid, 128, GEMM_SMEM>>>(h, w1h, b1, z);
    act_kernel<<<B_SZ, 256>>>(z, tids + H_SZ, m2, h, mout + BH);

    gemm_f16_nt<H_SZ><<<grid, 128, GEMM_SMEM>>>(h, w2h, b2, z);
    act_kernel<<<B_SZ, 256>>>(z, tids + 2 * H_SZ, m3, h, mout + 2 * BH);

    layer3_kernel<<<B_SZ / 64, 256>>>(h, W3, b3, out);
}